// round 1
// baseline (speedup 1.0000x reference)
#include <cuda_runtime.h>
#include <cstdint>

// Problem constants
#define B_   2
#define L_   2048
#define D_   2048
#define NH_  16
#define HD_  128
#define BH_  (B_ * NH_)
#define ML_  (B_ * L_)          // 4096 rows for projections

__device__ __align__(16) float g_q[(size_t)B_ * L_ * D_];
__device__ __align__(16) float g_k[(size_t)B_ * L_ * D_];
__device__ __align__(16) float g_v[(size_t)B_ * L_ * D_];
__device__ __align__(16) float g_attn[(size_t)B_ * L_ * D_];

// attention scale folded with log2(e) so softmax uses exp2
#define ATT_QSCALE (0.08838834764831845f * 1.4426950408889634f)

// ---------------------------------------------------------------------------
// Fast exp2 on the FMA pipe (avoids MUFU bottleneck). |err| ~2e-6 rel.
// Input expected <= ~0; clamped below -120 (result underflows to ~2^-120).
// ---------------------------------------------------------------------------
__device__ __forceinline__ float exp2p(float y) {
    y = fmaxf(y, -120.0f);
    float t = y + 12582912.0f;               // round-to-nearest integer trick
    int   i = __float_as_int(t);             // low bits hold round(y)
    float f = y - (t - 12582912.0f);         // f in [-0.5, 0.5]
    float p = 1.3333558e-3f;                 // ln2^5/120
    p = fmaf(p, f, 9.6181291e-3f);           // ln2^4/24
    p = fmaf(p, f, 5.5504109e-2f);           // ln2^3/6
    p = fmaf(p, f, 2.4022651e-1f);           // ln2^2/2
    p = fmaf(p, f, 6.9314718e-1f);           // ln2
    p = fmaf(p, f, 1.0f);
    return __int_as_float(__float_as_int(p) + (i << 23));
}

// ---------------------------------------------------------------------------
// SGEMM: C[M,N] = A[M,K] @ W[N,K]^T + bias[N]   (all row-major)
// 128x128 block tile, BK=8, 256 threads, 8x8 per-thread tile.
// ---------------------------------------------------------------------------
__global__ __launch_bounds__(256, 2)
void gemm_nt_bias(const float* __restrict__ A, const float* __restrict__ W,
                  const float* __restrict__ bias, float* __restrict__ C,
                  int M, int N, int K)
{
    __shared__ float As[8][128];
    __shared__ float Bs[8][128];

    const int tid  = threadIdx.x;
    const int tx   = tid & 15;
    const int ty   = tid >> 4;
    const int row0 = blockIdx.y * 128;
    const int col0 = blockIdx.x * 128;

    const int lrow = tid >> 1;          // 0..127
    const int lk   = (tid & 1) * 4;     // 0 or 4

    const float* Ap = A + (size_t)(row0 + lrow) * K + lk;
    const float* Wp = W + (size_t)(col0 + lrow) * K + lk;

    float acc[8][8];
    #pragma unroll
    for (int i = 0; i < 8; i++)
        #pragma unroll
        for (int j = 0; j < 8; j++) acc[i][j] = 0.0f;

    for (int k0 = 0; k0 < K; k0 += 8) {
        float4 av = *(const float4*)(Ap + k0);
        float4 wv = *(const float4*)(Wp + k0);
        __syncthreads();
        As[lk + 0][lrow] = av.x; As[lk + 1][lrow] = av.y;
        As[lk + 2][lrow] = av.z; As[lk + 3][lrow] = av.w;
        Bs[lk + 0][lrow] = wv.x; Bs[lk + 1][lrow] = wv.y;
        Bs[lk + 2][lrow] = wv.z; Bs[lk + 3][lrow] = wv.w;
        __syncthreads();

        #pragma unroll
        for (int kk = 0; kk < 8; kk++) {
            float4 a0 = *(const float4*)&As[kk][ty * 8];
            float4 a1 = *(const float4*)&As[kk][ty * 8 + 4];
            float4 b0 = *(const float4*)&Bs[kk][tx * 8];
            float4 b1 = *(const float4*)&Bs[kk][tx * 8 + 4];
            float ar[8] = {a0.x, a0.y, a0.z, a0.w, a1.x, a1.y, a1.z, a1.w};
            float br[8] = {b0.x, b0.y, b0.z, b0.w, b1.x, b1.y, b1.z, b1.w};
            #pragma unroll
            for (int i = 0; i < 8; i++)
                #pragma unroll
                for (int j = 0; j < 8; j++)
                    acc[i][j] = fmaf(ar[i], br[j], acc[i][j]);
        }
    }

    #pragma unroll
    for (int i = 0; i < 8; i++) {
        const int r = row0 + ty * 8 + i;
        #pragma unroll
        for (int j = 0; j < 8; j += 4) {
            const int c = col0 + tx * 8 + j;
            float4 o;
            o.x = acc[i][j + 0] + bias[c + 0];
            o.y = acc[i][j + 1] + bias[c + 1];
            o.z = acc[i][j + 2] + bias[c + 2];
            o.w = acc[i][j + 3] + bias[c + 3];
            *(float4*)&C[(size_t)r * N + c] = o;
        }
    }
}

// ---------------------------------------------------------------------------
// Flash attention (fp32, causal). BM=BN=128, HD=128. 256 threads = 16x16.
// Q stored transposed in smem (pre-scaled by SCALE*log2e); K transposed;
// V natural; K and V share one smem buffer. P staged through smem.
// ---------------------------------------------------------------------------
#define KV_STRIDE 132   // 128 + 4 pad (keeps float4 alignment, spreads banks)

extern __shared__ float satt[];

__global__ __launch_bounds__(256, 1)
void attn_kernel(const float* __restrict__ Q, const float* __restrict__ K,
                 const float* __restrict__ V, float* __restrict__ O)
{
    float* Qs  = satt;                          // [d][r]  128 x 132
    float* KVs = satt + 128 * KV_STRIDE;        // K:[d][c] then V:[j][c]
    float* Ps  = satt + 2 * 128 * KV_STRIDE;    // [r][j]  128 x 132

    const int tid = threadIdx.x;
    const int tx  = tid & 15;                   // key-col group (8 cols)
    const int ty  = tid >> 4;                   // query-row group (8 rows)
    const int qb  = blockIdx.x;                 // 0..15
    const int bh  = blockIdx.y;                 // 0..31
    const int b   = bh / NH_;
    const int h   = bh % NH_;
    const int q0  = qb * 128;
    const size_t base = (size_t)b * L_ * D_ + (size_t)h * HD_;

    // ---- load Q tile (transposed, pre-scaled) ----
    #pragma unroll
    for (int it = 0; it < 16; it++) {
        int idx = tid + it * 256;
        int r   = (idx >> 3) & 127;
        int d4  = ((idx & 7) << 2) + ((idx >> 10) << 5);
        float4 qv = *(const float4*)(Q + base + (size_t)(q0 + r) * D_ + d4);
        Qs[(d4 + 0) * KV_STRIDE + r] = qv.x * ATT_QSCALE;
        Qs[(d4 + 1) * KV_STRIDE + r] = qv.y * ATT_QSCALE;
        Qs[(d4 + 2) * KV_STRIDE + r] = qv.z * ATT_QSCALE;
        Qs[(d4 + 3) * KV_STRIDE + r] = qv.w * ATT_QSCALE;
    }

    float o[8][8];
    float m[8], l[8];
    #pragma unroll
    for (int i = 0; i < 8; i++) {
        m[i] = -3.0e38f; l[i] = 0.0f;
        #pragma unroll
        for (int j = 0; j < 8; j++) o[i][j] = 0.0f;
    }

    for (int t = 0; t <= qb; t++) {
        const int n0 = t * 128;

        // ---- load K tile (transposed) ----
        __syncthreads();   // prior PV done reading KVs
        #pragma unroll
        for (int it = 0; it < 16; it++) {
            int idx = tid + it * 256;
            int c   = (idx >> 3) & 127;
            int d4  = ((idx & 7) << 2) + ((idx >> 10) << 5);
            float4 kv = *(const float4*)(K + base + (size_t)(n0 + c) * D_ + d4);
            KVs[(d4 + 0) * KV_STRIDE + c] = kv.x;
            KVs[(d4 + 1) * KV_STRIDE + c] = kv.y;
            KVs[(d4 + 2) * KV_STRIDE + c] = kv.z;
            KVs[(d4 + 3) * KV_STRIDE + c] = kv.w;
        }
        __syncthreads();

        // ---- S = Qs^T @ Ks  (scaled scores, log2 units) ----
        float s[8][8];
        #pragma unroll
        for (int i = 0; i < 8; i++)
            #pragma unroll
            for (int j = 0; j < 8; j++) s[i][j] = 0.0f;

        #pragma unroll 4
        for (int d = 0; d < 128; d++) {
            float4 qa = *(const float4*)&Qs[d * KV_STRIDE + ty * 8];
            float4 qbv = *(const float4*)&Qs[d * KV_STRIDE + ty * 8 + 4];
            float4 ka = *(const float4*)&KVs[d * KV_STRIDE + tx * 8];
            float4 kb = *(const float4*)&KVs[d * KV_STRIDE + tx * 8 + 4];
            float qr[8] = {qa.x, qa.y, qa.z, qa.w, qbv.x, qbv.y, qbv.z, qbv.w};
            float kr[8] = {ka.x, ka.y, ka.z, ka.w, kb.x, kb.y, kb.z, kb.w};
            #pragma unroll
            for (int i = 0; i < 8; i++)
                #pragma unroll
                for (int j = 0; j < 8; j++)
                    s[i][j] = fmaf(qr[i], kr[j], s[i][j]);
        }

        // ---- causal mask on diagonal tile ----
        if (t == qb) {
            #pragma unroll
            for (int i = 0; i < 8; i++)
                #pragma unroll
                for (int j = 0; j < 8; j++)
                    if ((ty * 8 + i) < (tx * 8 + j)) s[i][j] = -1.0e30f;
        }

        // ---- online softmax update ----
        #pragma unroll
        for (int i = 0; i < 8; i++) {
            float mloc = s[i][0];
            #pragma unroll
            for (int j = 1; j < 8; j++) mloc = fmaxf(mloc, s[i][j]);
            #pragma unroll
            for (int w = 1; w < 16; w <<= 1)
                mloc = fmaxf(mloc, __shfl_xor_sync(0xffffffffu, mloc, w));
            float mnew  = fmaxf(m[i], mloc);
            float alpha = exp2p(m[i] - mnew);
            float rs = 0.0f;
            #pragma unroll
            for (int j = 0; j < 8; j++) {
                float p = exp2p(s[i][j] - mnew);
                s[i][j] = p;
                rs += p;
            }
            #pragma unroll
            for (int w = 1; w < 16; w <<= 1)
                rs += __shfl_xor_sync(0xffffffffu, rs, w);
            l[i] = l[i] * alpha + rs;
            m[i] = mnew;
            #pragma unroll
            for (int j = 0; j < 8; j++) o[i][j] *= alpha;

            *(float4*)&Ps[(ty * 8 + i) * KV_STRIDE + tx * 8] =
                make_float4(s[i][0], s[i][1], s[i][2], s[i][3]);
            *(float4*)&Ps[(ty * 8 + i) * KV_STRIDE + tx * 8 + 4] =
                make_float4(s[i][4], s[i][5], s[i][6], s[i][7]);
        }

        // ---- load V tile (natural layout) into same buffer ----
        __syncthreads();   // S-phase done reading KVs, Ps visible
        #pragma unroll
        for (int it = 0; it < 16; it++) {
            int idx = tid + it * 256;
            int j   = idx >> 5;
            int c4  = (idx & 31) << 2;
            float4 vv = *(const float4*)(V + base + (size_t)(n0 + j) * D_ + c4);
            *(float4*)&KVs[j * KV_STRIDE + c4] = vv;
        }
        __syncthreads();

        // ---- O += P @ V ----
        for (int j0 = 0; j0 < 128; j0 += 4) {
            float4 pr[8];
            #pragma unroll
            for (int i = 0; i < 8; i++)
                pr[i] = *(const float4*)&Ps[(ty * 8 + i) * KV_STRIDE + j0];
            #pragma unroll
            for (int jj = 0; jj < 4; jj++) {
                float4 va = *(const float4*)&KVs[(j0 + jj) * KV_STRIDE + tx * 8];
                float4 vb = *(const float4*)&KVs[(j0 + jj) * KV_STRIDE + tx * 8 + 4];
                float vr[8] = {va.x, va.y, va.z, va.w, vb.x, vb.y, vb.z, vb.w};
                float pj[8];
                #pragma unroll
                for (int i = 0; i < 8; i++)
                    pj[i] = (jj == 0) ? pr[i].x : (jj == 1) ? pr[i].y
                          : (jj == 2) ? pr[i].z : pr[i].w;
                #pragma unroll
                for (int i = 0; i < 8; i++)
                    #pragma unroll
                    for (int c = 0; c < 8; c++)
                        o[i][c] = fmaf(pj[i], vr[c], o[i][c]);
            }
        }
    }

    // ---- epilogue: normalize + write ----
    #pragma unroll
    for (int i = 0; i < 8; i++) {
        float inv = 1.0f / l[i];
        const int r = q0 + ty * 8 + i;
        float4 o0 = make_float4(o[i][0] * inv, o[i][1] * inv,
                                o[i][2] * inv, o[i][3] * inv);
        float4 o1 = make_float4(o[i][4] * inv, o[i][5] * inv,
                                o[i][6] * inv, o[i][7] * inv);
        *(float4*)&O[base + (size_t)r * D_ + tx * 8]     = o0;
        *(float4*)&O[base + (size_t)r * D_ + tx * 8 + 4] = o1;
    }
}

// ---------------------------------------------------------------------------
// Launcher
// ---------------------------------------------------------------------------
extern "C" void kernel_launch(void* const* d_in, const int* in_sizes, int n_in,
                              void* d_out, int out_size)
{
    const float* hs = (const float*)d_in[0];
    const float* Wq = (const float*)d_in[1];
    const float* bq = (const float*)d_in[2];
    const float* Wk = (const float*)d_in[3];
    const float* bk = (const float*)d_in[4];
    const float* Wv = (const float*)d_in[5];
    const float* bv = (const float*)d_in[6];
    const float* Wo = (const float*)d_in[7];
    const float* bo = (const float*)d_in[8];
    float* out = (float*)d_out;

    float *q, *k, *v, *attn;
    cudaGetSymbolAddress((void**)&q,    g_q);
    cudaGetSymbolAddress((void**)&k,    g_k);
    cudaGetSymbolAddress((void**)&v,    g_v);
    cudaGetSymbolAddress((void**)&attn, g_attn);

    dim3 gg(D_ / 128, ML_ / 128);   // (16, 32)

    gemm_nt_bias<<<gg, 256>>>(hs, Wq, bq, q, ML_, D_, D_);
    gemm_nt_bias<<<gg, 256>>>(hs, Wk, bk, k, ML_, D_, D_);
    gemm_nt_bias<<<gg, 256>>>(hs, Wv, bv, v, ML_, D_, D_);

    size_t smem = (size_t)3 * 128 * KV_STRIDE * sizeof(float);  // 202,752 B
    cudaFuncSetAttribute(attn_kernel,
                         cudaFuncAttributeMaxDynamicSharedMemorySize,
                         (int)smem);
    attn_kernel<<<dim3(L_ / 128, BH_), 256, smem>>>(q, k, v, attn);

    gemm_nt_bias<<<gg, 256>>>(attn, Wo, bo, out, ML_, D_, D_);
}

// round 4
// speedup vs baseline: 3.6218x; 3.6218x over previous
#include <cuda_runtime.h>
#include <cstdint>

// Problem constants
#define B_   2
#define L_   2048
#define D_   2048
#define NH_  16
#define HD_  128
#define BH_  (B_ * NH_)
#define ML_  (B_ * L_)          // 4096 rows for projections

// ---------------------------------------------------------------------------
// Scratch (static device allocations; no cudaMalloc allowed)
// ---------------------------------------------------------------------------
__device__ __align__(1024) float g_q[(size_t)ML_ * D_];
__device__ __align__(1024) float g_k[(size_t)ML_ * D_];
__device__ __align__(1024) float g_v[(size_t)ML_ * D_];
__device__ __align__(1024) float g_attn[(size_t)ML_ * D_];
__device__ __align__(1024) float g_hsr[(size_t)ML_ * D_];
__device__ __align__(1024) float g_wqr[(size_t)D_ * D_];
__device__ __align__(1024) float g_wkr[(size_t)D_ * D_];
__device__ __align__(1024) float g_wvr[(size_t)D_ * D_];
__device__ __align__(1024) float g_wor[(size_t)D_ * D_];

// attention scale folded with log2(e) so softmax uses exp2
#define ATT_QSCALE (0.08838834764831845f * 1.4426950408889634f)

// ---------------------------------------------------------------------------
// Helpers
// ---------------------------------------------------------------------------
__device__ __forceinline__ uint32_t smem_u32(const void* p) {
    uint32_t a;
    asm("{ .reg .u64 t; cvta.to.shared.u64 t, %1; cvt.u32.u64 %0, t; }"
        : "=r"(a) : "l"(p));
    return a;
}

__device__ __forceinline__ float tf32r(float x) {
    uint32_t u;
    asm("cvt.rna.tf32.f32 %0, %1;" : "=r"(u) : "f"(x));
    return __uint_as_float(u);
}

#define CP_ASYNC16(dst, src) \
    asm volatile("cp.async.cg.shared.global [%0], [%1], 16;" \
                 :: "r"(dst), "l"(src) : "memory")
#define CP_COMMIT() asm volatile("cp.async.commit_group;" ::: "memory")
#define CP_WAIT2()  asm volatile("cp.async.wait_group 2;" ::: "memory")

// mma.sync m16n8k8 tf32: D += A*B, A row-major m16k8, B col-major k8n8
#define MMA_TF32_16N8K8(c, a, b) \
    asm volatile("mma.sync.aligned.m16n8k8.row.col.f32.tf32.tf32.f32 " \
                 "{%0,%1,%2,%3}, {%4,%5,%6,%7}, {%8,%9}, {%0,%1,%2,%3};" \
                 : "+f"((c)[0]), "+f"((c)[1]), "+f"((c)[2]), "+f"((c)[3]) \
                 : "r"((a)[0]), "r"((a)[1]), "r"((a)[2]), "r"((a)[3]), \
                   "r"((b)[0]), "r"((b)[1]))

// ---------------------------------------------------------------------------
// Round-to-tf32 copy kernel (rounds GEMM operands to tf32-nearest once)
// ---------------------------------------------------------------------------
__global__ void round_tf32_kernel(const float* __restrict__ in,
                                  float* __restrict__ out, int n4)
{
    int i = blockIdx.x * blockDim.x + threadIdx.x;
    int stride = gridDim.x * blockDim.x;
    for (; i < n4; i += stride) {
        float4 v = ((const float4*)in)[i];
        v.x = tf32r(v.x); v.y = tf32r(v.y);
        v.z = tf32r(v.z); v.w = tf32r(v.w);
        ((float4*)out)[i] = v;
    }
}

// ---------------------------------------------------------------------------
// HMMA tf32 GEMM: C[M,2048] = A[M,2048] @ W[2048,2048]^T + bias
// BM=BN=128, BK=16, 4-stage cp.async pipeline, 256 threads = 8 warps.
// Warp grid 4x2: each warp computes 32 rows x 64 cols
// (2 m16 tiles x 8 n8 tiles of m16n8k8).
// Smem rows padded to 20 floats (80 B) -> conflict-free fragment loads,
// 16B-aligned cp.async destinations.
// ---------------------------------------------------------------------------
#define GBK     16
#define GSTG    4
#define ROWPAD  20                         // floats per smem row
#define TILE_FLOATS (128 * ROWPAD)         // 2560 floats per operand tile
#define STAGE_FLOATS (2 * TILE_FLOATS)     // A then B
#define GEMM_SMEM (GSTG * STAGE_FLOATS * 4)  // 81920 bytes

__global__ __launch_bounds__(256, 2)
void gemm_tf32mma(const float* __restrict__ A, const float* __restrict__ W,
                  const float* __restrict__ bias, float* __restrict__ C)
{
    extern __shared__ __align__(1024) float smf[];
    const uint32_t sb = smem_u32(smf);

    const int tid  = threadIdx.x;
    const int wid  = tid >> 5;
    const int lane = tid & 31;
    const int g    = lane >> 2;            // groupID   0..7
    const int tg   = lane & 3;             // thread-in-group 0..3
    const int wr   = wid >> 1;             // warp row 0..3 (32 rows each)
    const int wc   = wid & 1;              // warp col 0..1 (64 cols each)

    const int row0 = blockIdx.y * 128;
    const int col0 = blockIdx.x * 128;
    const int K    = D_;
    const int NIT  = K / GBK;              // 128

    const float* Ab = A + (size_t)row0 * K;
    const float* Wb = W + (size_t)col0 * K;

    // per-thread cp.async assignment: 4 chunks of 16B
    // idx in [0,1024): first 512 = A tile, next 512 = B tile
    // chunk -> (row = idx>>2, c4 = idx&3)
    int c_isB[4], c_row[4], c_c4[4];
    #pragma unroll
    for (int p = 0; p < 4; p++) {
        int idx = p * 256 + tid;
        c_isB[p] = idx >= 512;
        int id2  = idx & 511;
        c_row[p] = id2 >> 2;
        c_c4[p]  = id2 & 3;
    }

    auto issue = [&](int s, int it) {
        const int k0 = it * GBK;
        #pragma unroll
        for (int p = 0; p < 4; p++) {
            const float* src = (c_isB[p] ? Wb : Ab)
                               + (size_t)c_row[p] * K + k0 + c_c4[p] * 4;
            uint32_t dst = sb + (uint32_t)(s * STAGE_FLOATS
                              + c_isB[p] * TILE_FLOATS
                              + c_row[p] * ROWPAD + c_c4[p] * 4) * 4u;
            CP_ASYNC16(dst, src);
        }
    };

    float acc[2][8][4];
    #pragma unroll
    for (int mt = 0; mt < 2; mt++)
        #pragma unroll
        for (int nt = 0; nt < 8; nt++)
            #pragma unroll
            for (int e = 0; e < 4; e++) acc[mt][nt][e] = 0.0f;

    // prefetch 3 stages
    #pragma unroll
    for (int s = 0; s < GSTG - 1; s++) { issue(s, s); CP_COMMIT(); }

    for (int it = 0; it < NIT; it++) {
        CP_WAIT2();
        __syncthreads();

        const int s = it & (GSTG - 1);
        const float* As = smf + s * STAGE_FLOATS;
        const float* Bs = As + TILE_FLOATS;

        #pragma unroll
        for (int ks = 0; ks < 2; ks++) {
            const int kb = ks * 8;
            uint32_t af[2][4];
            #pragma unroll
            for (int mt = 0; mt < 2; mt++) {
                const int rb = wr * 32 + mt * 16;
                af[mt][0] = __float_as_uint(As[(rb + g)     * ROWPAD + kb + tg]);
                af[mt][1] = __float_as_uint(As[(rb + g + 8) * ROWPAD + kb + tg]);
                af[mt][2] = __float_as_uint(As[(rb + g)     * ROWPAD + kb + tg + 4]);
                af[mt][3] = __float_as_uint(As[(rb + g + 8) * ROWPAD + kb + tg + 4]);
            }
            uint32_t bf[8][2];
            #pragma unroll
            for (int nt = 0; nt < 8; nt++) {
                const int cb = wc * 64 + nt * 8;
                bf[nt][0] = __float_as_uint(Bs[(cb + g) * ROWPAD + kb + tg]);
                bf[nt][1] = __float_as_uint(Bs[(cb + g) * ROWPAD + kb + tg + 4]);
            }
            #pragma unroll
            for (int mt = 0; mt < 2; mt++)
                #pragma unroll
                for (int nt = 0; nt < 8; nt++)
                    MMA_TF32_16N8K8(acc[mt][nt], af[mt], bf[nt]);
        }

        __syncthreads();
        if (it + GSTG - 1 < NIT) issue((it + GSTG - 1) & (GSTG - 1), it + GSTG - 1);
        CP_COMMIT();
    }

    // epilogue: bias add + store (each c-pair is a contiguous float2)
    #pragma unroll
    for (int mt = 0; mt < 2; mt++) {
        const int r0 = row0 + wr * 32 + mt * 16 + g;
        #pragma unroll
        for (int nt = 0; nt < 8; nt++) {
            const int c = col0 + wc * 64 + nt * 8 + tg * 2;
            float2 bb = *(const float2*)&bias[c];
            float2 o0 = make_float2(acc[mt][nt][0] + bb.x, acc[mt][nt][1] + bb.y);
            float2 o1 = make_float2(acc[mt][nt][2] + bb.x, acc[mt][nt][3] + bb.y);
            *(float2*)&C[(size_t)r0 * D_ + c]       = o0;
            *(float2*)&C[(size_t)(r0 + 8) * D_ + c] = o1;
        }
    }
}

// ---------------------------------------------------------------------------
// Fast exp2 on the FMA pipe. |err| ~2e-6 rel.
// ---------------------------------------------------------------------------
__device__ __forceinline__ float exp2p(float y) {
    y = fmaxf(y, -120.0f);
    float t = y + 12582912.0f;
    int   i = __float_as_int(t);
    float f = y - (t - 12582912.0f);
    float p = 1.3333558e-3f;
    p = fmaf(p, f, 9.6181291e-3f);
    p = fmaf(p, f, 5.5504109e-2f);
    p = fmaf(p, f, 2.4022651e-1f);
    p = fmaf(p, f, 6.9314718e-1f);
    p = fmaf(p, f, 1.0f);
    return __int_as_float(__float_as_int(p) + (i << 23));
}

// ---------------------------------------------------------------------------
// Flash attention (fp32, causal). BM=BN=128, HD=128. 256 threads = 16x16.
// Output rounded to tf32 (it feeds the tf32 O-projection).
// ---------------------------------------------------------------------------
#define KV_STRIDE 132

extern __shared__ float satt[];

__global__ __launch_bounds__(256, 1)
void attn_kernel(const float* __restrict__ Q, const float* __restrict__ K,
                 const float* __restrict__ V, float* __restrict__ O)
{
    float* Qs  = satt;
    float* KVs = satt + 128 * KV_STRIDE;
    float* Ps  = satt + 2 * 128 * KV_STRIDE;

    const int tid = threadIdx.x;
    const int tx  = tid & 15;
    const int ty  = tid >> 4;
    const int qb  = blockIdx.x;
    const int bh  = blockIdx.y;
    const int b   = bh / NH_;
    const int h   = bh % NH_;
    const int q0  = qb * 128;
    const size_t base = (size_t)b * L_ * D_ + (size_t)h * HD_;

    #pragma unroll
    for (int it = 0; it < 16; it++) {
        int idx = tid + it * 256;
        int r   = (idx >> 3) & 127;
        int d4  = ((idx & 7) << 2) + ((idx >> 10) << 5);
        float4 qv = *(const float4*)(Q + base + (size_t)(q0 + r) * D_ + d4);
        Qs[(d4 + 0) * KV_STRIDE + r] = qv.x * ATT_QSCALE;
        Qs[(d4 + 1) * KV_STRIDE + r] = qv.y * ATT_QSCALE;
        Qs[(d4 + 2) * KV_STRIDE + r] = qv.z * ATT_QSCALE;
        Qs[(d4 + 3) * KV_STRIDE + r] = qv.w * ATT_QSCALE;
    }

    float o[8][8];
    float m[8], l[8];
    #pragma unroll
    for (int i = 0; i < 8; i++) {
        m[i] = -3.0e38f; l[i] = 0.0f;
        #pragma unroll
        for (int j = 0; j < 8; j++) o[i][j] = 0.0f;
    }

    for (int t = 0; t <= qb; t++) {
        const int n0 = t * 128;

        __syncthreads();
        #pragma unroll
        for (int it = 0; it < 16; it++) {
            int idx = tid + it * 256;
            int c   = (idx >> 3) & 127;
            int d4  = ((idx & 7) << 2) + ((idx >> 10) << 5);
            float4 kv = *(const float4*)(K + base + (size_t)(n0 + c) * D_ + d4);
            KVs[(d4 + 0) * KV_STRIDE + c] = kv.x;
            KVs[(d4 + 1) * KV_STRIDE + c] = kv.y;
            KVs[(d4 + 2) * KV_STRIDE + c] = kv.z;
            KVs[(d4 + 3) * KV_STRIDE + c] = kv.w;
        }
        __syncthreads();

        float s[8][8];
        #pragma unroll
        for (int i = 0; i < 8; i++)
            #pragma unroll
            for (int j = 0; j < 8; j++) s[i][j] = 0.0f;

        #pragma unroll 4
        for (int d = 0; d < 128; d++) {
            float4 qa  = *(const float4*)&Qs[d * KV_STRIDE + ty * 8];
            float4 qbv = *(const float4*)&Qs[d * KV_STRIDE + ty * 8 + 4];
            float4 ka  = *(const float4*)&KVs[d * KV_STRIDE + tx * 8];
            float4 kb  = *(const float4*)&KVs[d * KV_STRIDE + tx * 8 + 4];
            float qr[8] = {qa.x, qa.y, qa.z, qa.w, qbv.x, qbv.y, qbv.z, qbv.w};
            float kr[8] = {ka.x, ka.y, ka.z, ka.w, kb.x, kb.y, kb.z, kb.w};
            #pragma unroll
            for (int i = 0; i < 8; i++)
                #pragma unroll
                for (int j = 0; j < 8; j++)
                    s[i][j] = fmaf(qr[i], kr[j], s[i][j]);
        }

        if (t == qb) {
            #pragma unroll
            for (int i = 0; i < 8; i++)
                #pragma unroll
                for (int j = 0; j < 8; j++)
                    if ((ty * 8 + i) < (tx * 8 + j)) s[i][j] = -1.0e30f;
        }

        #pragma unroll
        for (int i = 0; i < 8; i++) {
            float mloc = s[i][0];
            #pragma unroll
            for (int j = 1; j < 8; j++) mloc = fmaxf(mloc, s[i][j]);
            #pragma unroll
            for (int w = 1; w < 16; w <<= 1)
                mloc = fmaxf(mloc, __shfl_xor_sync(0xffffffffu, mloc, w));
            float mnew  = fmaxf(m[i], mloc);
            float alpha = exp2p(m[i] - mnew);
            float rs = 0.0f;
            #pragma unroll
            for (int j = 0; j < 8; j++) {
                float p = exp2p(s[i][j] - mnew);
                s[i][j] = p;
                rs += p;
            }
            #pragma unroll
            for (int w = 1; w < 16; w <<= 1)
                rs += __shfl_xor_sync(0xffffffffu, rs, w);
            l[i] = l[i] * alpha + rs;
            m[i] = mnew;
            #pragma unroll
            for (int j = 0; j < 8; j++) o[i][j] *= alpha;

            *(float4*)&Ps[(ty * 8 + i) * KV_STRIDE + tx * 8] =
                make_float4(s[i][0], s[i][1], s[i][2], s[i][3]);
            *(float4*)&Ps[(ty * 8 + i) * KV_STRIDE + tx * 8 + 4] =
                make_float4(s[i][4], s[i][5], s[i][6], s[i][7]);
        }

        __syncthreads();
        #pragma unroll
        for (int it = 0; it < 16; it++) {
            int idx = tid + it * 256;
            int j   = idx >> 5;
            int c4  = (idx & 31) << 2;
            float4 vv = *(const float4*)(V + base + (size_t)(n0 + j) * D_ + c4);
            *(float4*)&KVs[j * KV_STRIDE + c4] = vv;
        }
        __syncthreads();

        for (int j0 = 0; j0 < 128; j0 += 4) {
            float4 pr[8];
            #pragma unroll
            for (int i = 0; i < 8; i++)
                pr[i] = *(const float4*)&Ps[(ty * 8 + i) * KV_STRIDE + j0];
            #pragma unroll
            for (int jj = 0; jj < 4; jj++) {
                float4 va = *(const float4*)&KVs[(j0 + jj) * KV_STRIDE + tx * 8];
                float4 vb = *(const float4*)&KVs[(j0 + jj) * KV_STRIDE + tx * 8 + 4];
                float vr[8] = {va.x, va.y, va.z, va.w, vb.x, vb.y, vb.z, vb.w};
                float pj[8];
                #pragma unroll
                for (int i = 0; i < 8; i++)
                    pj[i] = (jj == 0) ? pr[i].x : (jj == 1) ? pr[i].y
                          : (jj == 2) ? pr[i].z : pr[i].w;
                #pragma unroll
                for (int i = 0; i < 8; i++)
                    #pragma unroll
                    for (int c = 0; c < 8; c++)
                        o[i][c] = fmaf(pj[i], vr[c], o[i][c]);
            }
        }
    }

    #pragma unroll
    for (int i = 0; i < 8; i++) {
        float inv = 1.0f / l[i];
        const int r = q0 + ty * 8 + i;
        float4 o0 = make_float4(tf32r(o[i][0] * inv), tf32r(o[i][1] * inv),
                                tf32r(o[i][2] * inv), tf32r(o[i][3] * inv));
        float4 o1 = make_float4(tf32r(o[i][4] * inv), tf32r(o[i][5] * inv),
                                tf32r(o[i][6] * inv), tf32r(o[i][7] * inv));
        *(float4*)&O[base + (size_t)r * D_ + tx * 8]     = o0;
        *(float4*)&O[base + (size_t)r * D_ + tx * 8 + 4] = o1;
    }
}

// ---------------------------------------------------------------------------
// Launcher
// ---------------------------------------------------------------------------
extern "C" void kernel_launch(void* const* d_in, const int* in_sizes, int n_in,
                              void* d_out, int out_size)
{
    const float* hs = (const float*)d_in[0];
    const float* Wq = (const float*)d_in[1];
    const float* bq = (const float*)d_in[2];
    const float* Wk = (const float*)d_in[3];
    const float* bk = (const float*)d_in[4];
    const float* Wv = (const float*)d_in[5];
    const float* bv = (const float*)d_in[6];
    const float* Wo = (const float*)d_in[7];
    const float* bo = (const float*)d_in[8];
    float* out = (float*)d_out;

    float *q, *k, *v, *attn, *hsr, *wqr, *wkr, *wvr, *wor;
    cudaGetSymbolAddress((void**)&q,    g_q);
    cudaGetSymbolAddress((void**)&k,    g_k);
    cudaGetSymbolAddress((void**)&v,    g_v);
    cudaGetSymbolAddress((void**)&attn, g_attn);
    cudaGetSymbolAddress((void**)&hsr,  g_hsr);
    cudaGetSymbolAddress((void**)&wqr,  g_wqr);
    cudaGetSymbolAddress((void**)&wkr,  g_wkr);
    cudaGetSymbolAddress((void**)&wvr,  g_wvr);
    cudaGetSymbolAddress((void**)&wor,  g_wor);

    // round all GEMM operands to tf32-nearest
    const int nHS4 = ML_ * D_ / 4;
    const int nW4  = D_ * D_ / 4;
    round_tf32_kernel<<<2048, 256>>>(hs, hsr, nHS4);
    round_tf32_kernel<<<2048, 256>>>(Wq, wqr, nW4);
    round_tf32_kernel<<<2048, 256>>>(Wk, wkr, nW4);
    round_tf32_kernel<<<2048, 256>>>(Wv, wvr, nW4);
    round_tf32_kernel<<<2048, 256>>>(Wo, wor, nW4);

    cudaFuncSetAttribute(gemm_tf32mma,
                         cudaFuncAttributeMaxDynamicSharedMemorySize, GEMM_SMEM);
    dim3 gg(D_ / 128, ML_ / 128);   // (16, 32)
    gemm_tf32mma<<<gg, 256, GEMM_SMEM>>>(hsr, wqr, bq, q);
    gemm_tf32mma<<<gg, 256, GEMM_SMEM>>>(hsr, wkr, bk, k);
    gemm_tf32mma<<<gg, 256, GEMM_SMEM>>>(hsr, wvr, bv, v);

    size_t smem = (size_t)3 * 128 * KV_STRIDE * sizeof(float);  // 202,752 B
    cudaFuncSetAttribute(attn_kernel,
                         cudaFuncAttributeMaxDynamicSharedMemorySize,
                         (int)smem);
    attn_kernel<<<dim3(L_ / 128, BH_), 256, smem>>>(q, k, v, attn);

    gemm_tf32mma<<<gg, 256, GEMM_SMEM>>>(attn, wor, bo, out);
}

// round 7
// speedup vs baseline: 5.2428x; 1.4475x over previous
#include <cuda_runtime.h>
#include <cstdint>

// Problem constants
#define B_   2
#define L_   2048
#define D_   2048
#define NH_  16
#define HD_  128
#define BH_  (B_ * NH_)
#define ML_  (B_ * L_)          // 4096 rows for projections

// ---------------------------------------------------------------------------
// Scratch (static device allocations; no cudaMalloc allowed)
// ---------------------------------------------------------------------------
__device__ __align__(1024) float g_q[(size_t)ML_ * D_];
__device__ __align__(1024) float g_k[(size_t)ML_ * D_];
__device__ __align__(1024) float g_v[(size_t)ML_ * D_];
__device__ __align__(1024) float g_attn[(size_t)ML_ * D_];
__device__ __align__(1024) float g_hsr[(size_t)ML_ * D_];
__device__ __align__(1024) float g_wqr[(size_t)D_ * D_];
__device__ __align__(1024) float g_wkr[(size_t)D_ * D_];
__device__ __align__(1024) float g_wvr[(size_t)D_ * D_];
__device__ __align__(1024) float g_wor[(size_t)D_ * D_];

// attention scale folded with log2(e) so softmax uses exp2
#define ATT_QSCALE (0.08838834764831845f * 1.4426950408889634f)

// ---------------------------------------------------------------------------
// Helpers
// ---------------------------------------------------------------------------
__device__ __forceinline__ uint32_t smem_u32(const void* p) {
    uint32_t a;
    asm("{ .reg .u64 t; cvta.to.shared.u64 t, %1; cvt.u32.u64 %0, t; }"
        : "=r"(a) : "l"(p));
    return a;
}

__device__ __forceinline__ float tf32r(float x) {
    uint32_t u;
    asm("cvt.rna.tf32.f32 %0, %1;" : "=r"(u) : "f"(x));
    return __uint_as_float(u);
}

#define CP_ASYNC16(dst, src) \
    asm volatile("cp.async.cg.shared.global [%0], [%1], 16;" \
                 :: "r"(dst), "l"(src) : "memory")
#define CP_COMMIT() asm volatile("cp.async.commit_group;" ::: "memory")
#define CP_WAIT2()  asm volatile("cp.async.wait_group 2;" ::: "memory")

// mma.sync m16n8k8 tf32: D += A*B, A row-major m16k8, B col-major k8n8
#define MMA_TF32_16N8K8(c, a, b) \
    asm volatile("mma.sync.aligned.m16n8k8.row.col.f32.tf32.tf32.f32 " \
                 "{%0,%1,%2,%3}, {%4,%5,%6,%7}, {%8,%9}, {%0,%1,%2,%3};" \
                 : "+f"((c)[0]), "+f"((c)[1]), "+f"((c)[2]), "+f"((c)[3]) \
                 : "r"((a)[0]), "r"((a)[1]), "r"((a)[2]), "r"((a)[3]), \
                   "r"((b)[0]), "r"((b)[1]))

// ---------------------------------------------------------------------------
// Round-to-tf32 copy kernel (rounds GEMM operands to tf32-nearest once)
// ---------------------------------------------------------------------------
__global__ void round_tf32_kernel(const float* __restrict__ in,
                                  float* __restrict__ out, int n4)
{
    int i = blockIdx.x * blockDim.x + threadIdx.x;
    int stride = gridDim.x * blockDim.x;
    for (; i < n4; i += stride) {
        float4 v = ((const float4*)in)[i];
        v.x = tf32r(v.x); v.y = tf32r(v.y);
        v.z = tf32r(v.z); v.w = tf32r(v.w);
        ((float4*)out)[i] = v;
    }
}

// ---------------------------------------------------------------------------
// HMMA tf32 GEMM: C[M,2048] = A[M,2048] @ W[2048,2048]^T + bias
// (unchanged from the passing R4 kernel)
// ---------------------------------------------------------------------------
#define GBK     16
#define GSTG    4
#define ROWPAD  20
#define TILE_FLOATS (128 * ROWPAD)
#define STAGE_FLOATS (2 * TILE_FLOATS)
#define GEMM_SMEM (GSTG * STAGE_FLOATS * 4)  // 81920 bytes

__global__ __launch_bounds__(256, 2)
void gemm_tf32mma(const float* __restrict__ A, const float* __restrict__ W,
                  const float* __restrict__ bias, float* __restrict__ C)
{
    extern __shared__ __align__(1024) float smf[];
    const uint32_t sb = smem_u32(smf);

    const int tid  = threadIdx.x;
    const int wid  = tid >> 5;
    const int lane = tid & 31;
    const int g    = lane >> 2;
    const int tg   = lane & 3;
    const int wr   = wid >> 1;
    const int wc   = wid & 1;

    const int row0 = blockIdx.y * 128;
    const int col0 = blockIdx.x * 128;
    const int K    = D_;
    const int NIT  = K / GBK;

    const float* Ab = A + (size_t)row0 * K;
    const float* Wb = W + (size_t)col0 * K;

    int c_isB[4], c_row[4], c_c4[4];
    #pragma unroll
    for (int p = 0; p < 4; p++) {
        int idx = p * 256 + tid;
        c_isB[p] = idx >= 512;
        int id2  = idx & 511;
        c_row[p] = id2 >> 2;
        c_c4[p]  = id2 & 3;
    }

    auto issue = [&](int s, int it) {
        const int k0 = it * GBK;
        #pragma unroll
        for (int p = 0; p < 4; p++) {
            const float* src = (c_isB[p] ? Wb : Ab)
                               + (size_t)c_row[p] * K + k0 + c_c4[p] * 4;
            uint32_t dst = sb + (uint32_t)(s * STAGE_FLOATS
                              + c_isB[p] * TILE_FLOATS
                              + c_row[p] * ROWPAD + c_c4[p] * 4) * 4u;
            CP_ASYNC16(dst, src);
        }
    };

    float acc[2][8][4];
    #pragma unroll
    for (int mt = 0; mt < 2; mt++)
        #pragma unroll
        for (int nt = 0; nt < 8; nt++)
            #pragma unroll
            for (int e = 0; e < 4; e++) acc[mt][nt][e] = 0.0f;

    #pragma unroll
    for (int s = 0; s < GSTG - 1; s++) { issue(s, s); CP_COMMIT(); }

    for (int it = 0; it < NIT; it++) {
        CP_WAIT2();
        __syncthreads();

        const int s = it & (GSTG - 1);
        const float* As = smf + s * STAGE_FLOATS;
        const float* Bs = As + TILE_FLOATS;

        #pragma unroll
        for (int ks = 0; ks < 2; ks++) {
            const int kb = ks * 8;
            uint32_t af[2][4];
            #pragma unroll
            for (int mt = 0; mt < 2; mt++) {
                const int rb = wr * 32 + mt * 16;
                af[mt][0] = __float_as_uint(As[(rb + g)     * ROWPAD + kb + tg]);
                af[mt][1] = __float_as_uint(As[(rb + g + 8) * ROWPAD + kb + tg]);
                af[mt][2] = __float_as_uint(As[(rb + g)     * ROWPAD + kb + tg + 4]);
                af[mt][3] = __float_as_uint(As[(rb + g + 8) * ROWPAD + kb + tg + 4]);
            }
            uint32_t bf[8][2];
            #pragma unroll
            for (int nt = 0; nt < 8; nt++) {
                const int cb = wc * 64 + nt * 8;
                bf[nt][0] = __float_as_uint(Bs[(cb + g) * ROWPAD + kb + tg]);
                bf[nt][1] = __float_as_uint(Bs[(cb + g) * ROWPAD + kb + tg + 4]);
            }
            #pragma unroll
            for (int mt = 0; mt < 2; mt++)
                #pragma unroll
                for (int nt = 0; nt < 8; nt++)
                    MMA_TF32_16N8K8(acc[mt][nt], af[mt], bf[nt]);
        }

        __syncthreads();
        if (it + GSTG - 1 < NIT) issue((it + GSTG - 1) & (GSTG - 1), it + GSTG - 1);
        CP_COMMIT();
    }

    #pragma unroll
    for (int mt = 0; mt < 2; mt++) {
        const int r0 = row0 + wr * 32 + mt * 16 + g;
        #pragma unroll
        for (int nt = 0; nt < 8; nt++) {
            const int c = col0 + wc * 64 + nt * 8 + tg * 2;
            float2 bb = *(const float2*)&bias[c];
            float2 o0 = make_float2(acc[mt][nt][0] + bb.x, acc[mt][nt][1] + bb.y);
            float2 o1 = make_float2(acc[mt][nt][2] + bb.x, acc[mt][nt][3] + bb.y);
            *(float2*)&C[(size_t)r0 * D_ + c]       = o0;
            *(float2*)&C[(size_t)(r0 + 8) * D_ + c] = o1;
        }
    }
}

// ---------------------------------------------------------------------------
// Fast exp2 on the FMA pipe. |err| ~2e-6 rel.
// ---------------------------------------------------------------------------
__device__ __forceinline__ float exp2p(float y) {
    y = fmaxf(y, -120.0f);
    float t = y + 12582912.0f;
    int   i = __float_as_int(t);
    float f = y - (t - 12582912.0f);
    float p = 1.3333558e-3f;
    p = fmaf(p, f, 9.6181291e-3f);
    p = fmaf(p, f, 5.5504109e-2f);
    p = fmaf(p, f, 2.4022651e-1f);
    p = fmaf(p, f, 6.9314718e-1f);
    p = fmaf(p, f, 1.0f);
    return __int_as_float(__float_as_int(p) + (i << 23));
}

// ---------------------------------------------------------------------------
// Flash attention with tf32 mma.sync (causal). BM=BN=128, HD=128.
// 256 threads = 8 warps; warp w owns query rows [w*16, w*16+16).
// Qs: [r][d] natural (A operand). Ks: [c][d] natural (B operand [n][k]).
// Vs: [c][j] transposed (B operand, n=headdim, k=key). Ps: [r][j] (A operand).
// All smem operands tf32-rounded; stride 132 floats -> conflict-free frags.
// ---------------------------------------------------------------------------
#define AST 132

extern __shared__ float satt[];

__global__ __launch_bounds__(256, 1)
void attn_mma(const float* __restrict__ Q, const float* __restrict__ K,
              const float* __restrict__ V, float* __restrict__ O)
{
    float* Qs  = satt;                       // 128 x AST
    float* KVs = satt + 128 * AST;           // K natural, then V transposed
    float* Ps  = satt + 2 * 128 * AST;       // P [r][j]

    const int tid  = threadIdx.x;
    const int w    = tid >> 5;
    const int lane = tid & 31;
    const int g    = lane >> 2;
    const int tg   = lane & 3;
    const int rb   = w * 16;                 // warp's query-row base in tile

    const int qb = blockIdx.x;
    const int bh = blockIdx.y;
    const int b  = bh / NH_;
    const int h  = bh % NH_;
    const int q0 = qb * 128;
    const size_t base = (size_t)b * L_ * D_ + (size_t)h * HD_;

    // ---- load Q tile: natural [r][d], scaled + tf32-rounded ----
    #pragma unroll
    for (int it = 0; it < 16; it++) {
        int idx = it * 256 + tid;
        int r   = idx >> 5;
        int c4  = (idx & 31) << 2;
        float4 qv = *(const float4*)(Q + base + (size_t)(q0 + r) * D_ + c4);
        float4 o;
        o.x = tf32r(qv.x * ATT_QSCALE); o.y = tf32r(qv.y * ATT_QSCALE);
        o.z = tf32r(qv.z * ATT_QSCALE); o.w = tf32r(qv.w * ATT_QSCALE);
        *(float4*)&Qs[r * AST + c4] = o;
    }

    float o_[16][4];
    float m0 = -3.0e38f, m1 = -3.0e38f, l0 = 0.0f, l1 = 0.0f;
    #pragma unroll
    for (int nt = 0; nt < 16; nt++)
        #pragma unroll
        for (int e = 0; e < 4; e++) o_[nt][e] = 0.0f;

    for (int t = 0; t <= qb; t++) {
        const int n0 = t * 128;

        // ---- load K tile natural [c][d], tf32-rounded ----
        __syncthreads();   // prior PV done reading KVs
        #pragma unroll
        for (int it = 0; it < 16; it++) {
            int idx = it * 256 + tid;
            int c   = idx >> 5;
            int c4  = (idx & 31) << 2;
            float4 kv = *(const float4*)(K + base + (size_t)(n0 + c) * D_ + c4);
            float4 o;
            o.x = tf32r(kv.x); o.y = tf32r(kv.y);
            o.z = tf32r(kv.z); o.w = tf32r(kv.w);
            *(float4*)&KVs[c * AST + c4] = o;
        }
        __syncthreads();

        // ---- S = Q K^T via mma (scores in log2 units) ----
        float sf[16][4];
        #pragma unroll
        for (int nt = 0; nt < 16; nt++)
            #pragma unroll
            for (int e = 0; e < 4; e++) sf[nt][e] = 0.0f;

        #pragma unroll
        for (int ks = 0; ks < 16; ks++) {
            const int kb = ks * 8;
            uint32_t af[4];
            af[0] = __float_as_uint(Qs[(rb + g)     * AST + kb + tg]);
            af[1] = __float_as_uint(Qs[(rb + g + 8) * AST + kb + tg]);
            af[2] = __float_as_uint(Qs[(rb + g)     * AST + kb + tg + 4]);
            af[3] = __float_as_uint(Qs[(rb + g + 8) * AST + kb + tg + 4]);
            #pragma unroll
            for (int nt = 0; nt < 16; nt++) {
                uint32_t bf[2];
                bf[0] = __float_as_uint(KVs[(nt * 8 + g) * AST + kb + tg]);
                bf[1] = __float_as_uint(KVs[(nt * 8 + g) * AST + kb + tg + 4]);
                MMA_TF32_16N8K8(sf[nt], af, bf);
            }
        }

        // ---- causal mask on diagonal tile ----
        if (t == qb) {
            #pragma unroll
            for (int nt = 0; nt < 16; nt++) {
                const int c0 = nt * 8 + 2 * tg;
                const int r0r = rb + g, r1r = rb + g + 8;
                if (r0r < c0)     sf[nt][0] = -1.0e30f;
                if (r0r < c0 + 1) sf[nt][1] = -1.0e30f;
                if (r1r < c0)     sf[nt][2] = -1.0e30f;
                if (r1r < c0 + 1) sf[nt][3] = -1.0e30f;
            }
        }

        // ---- online softmax on fragments ----
        float ml0 = -3.0e38f, ml1 = -3.0e38f;
        #pragma unroll
        for (int nt = 0; nt < 16; nt++) {
            ml0 = fmaxf(ml0, fmaxf(sf[nt][0], sf[nt][1]));
            ml1 = fmaxf(ml1, fmaxf(sf[nt][2], sf[nt][3]));
        }
        ml0 = fmaxf(ml0, __shfl_xor_sync(0xffffffffu, ml0, 1));
        ml0 = fmaxf(ml0, __shfl_xor_sync(0xffffffffu, ml0, 2));
        ml1 = fmaxf(ml1, __shfl_xor_sync(0xffffffffu, ml1, 1));
        ml1 = fmaxf(ml1, __shfl_xor_sync(0xffffffffu, ml1, 2));

        const float mn0 = fmaxf(m0, ml0), mn1 = fmaxf(m1, ml1);
        const float a0 = exp2p(m0 - mn0), a1 = exp2p(m1 - mn1);
        float rs0 = 0.0f, rs1 = 0.0f;
        #pragma unroll
        for (int nt = 0; nt < 16; nt++) {
            float p0 = exp2p(sf[nt][0] - mn0);
            float p1 = exp2p(sf[nt][1] - mn0);
            float p2 = exp2p(sf[nt][2] - mn1);
            float p3 = exp2p(sf[nt][3] - mn1);
            rs0 += p0 + p1; rs1 += p2 + p3;
            // store tf32-rounded P to smem (A operand for PV)
            *(float2*)&Ps[(rb + g)     * AST + nt * 8 + 2 * tg] =
                make_float2(tf32r(p0), tf32r(p1));
            *(float2*)&Ps[(rb + g + 8) * AST + nt * 8 + 2 * tg] =
                make_float2(tf32r(p2), tf32r(p3));
        }
        rs0 += __shfl_xor_sync(0xffffffffu, rs0, 1);
        rs0 += __shfl_xor_sync(0xffffffffu, rs0, 2);
        rs1 += __shfl_xor_sync(0xffffffffu, rs1, 1);
        rs1 += __shfl_xor_sync(0xffffffffu, rs1, 2);
        l0 = l0 * a0 + rs0; l1 = l1 * a1 + rs1;
        m0 = mn0; m1 = mn1;
        #pragma unroll
        for (int nt = 0; nt < 16; nt++) {
            o_[nt][0] *= a0; o_[nt][1] *= a0;
            o_[nt][2] *= a1; o_[nt][3] *= a1;
        }

        // ---- load V tile transposed [c][j], tf32-rounded ----
        __syncthreads();   // QK done reading K; Ps writes now visible to all
        #pragma unroll
        for (int it = 0; it < 16; it++) {
            int idx = it * 256 + tid;
            int j   = (idx >> 3) & 127;
            int c4  = ((idx & 7) << 2) + ((idx >> 10) << 5);
            float4 vv = *(const float4*)(V + base + (size_t)(n0 + j) * D_ + c4);
            KVs[(c4 + 0) * AST + j] = tf32r(vv.x);
            KVs[(c4 + 1) * AST + j] = tf32r(vv.y);
            KVs[(c4 + 2) * AST + j] = tf32r(vv.z);
            KVs[(c4 + 3) * AST + j] = tf32r(vv.w);
        }
        __syncthreads();

        // ---- O += P @ V via mma ----
        #pragma unroll
        for (int ks = 0; ks < 16; ks++) {
            const int kb = ks * 8;
            uint32_t af[4];
            af[0] = __float_as_uint(Ps[(rb + g)     * AST + kb + tg]);
            af[1] = __float_as_uint(Ps[(rb + g + 8) * AST + kb + tg]);
            af[2] = __float_as_uint(Ps[(rb + g)     * AST + kb + tg + 4]);
            af[3] = __float_as_uint(Ps[(rb + g + 8) * AST + kb + tg + 4]);
            #pragma unroll
            for (int nt = 0; nt < 16; nt++) {
                uint32_t bf[2];
                bf[0] = __float_as_uint(KVs[(nt * 8 + g) * AST + kb + tg]);
                bf[1] = __float_as_uint(KVs[(nt * 8 + g) * AST + kb + tg + 4]);
                MMA_TF32_16N8K8(o_[nt], af, bf);
            }
        }
    }

    // ---- epilogue: normalize + tf32-round + write ----
    const float inv0 = 1.0f / l0, inv1 = 1.0f / l1;
    const int gr0 = q0 + rb + g, gr1 = gr0 + 8;
    #pragma unroll
    for (int nt = 0; nt < 16; nt++) {
        const int c = nt * 8 + 2 * tg;
        *(float2*)&O[base + (size_t)gr0 * D_ + c] =
            make_float2(tf32r(o_[nt][0] * inv0), tf32r(o_[nt][1] * inv0));
        *(float2*)&O[base + (size_t)gr1 * D_ + c] =
            make_float2(tf32r(o_[nt][2] * inv1), tf32r(o_[nt][3] * inv1));
    }
}

// ---------------------------------------------------------------------------
// Launcher
// ---------------------------------------------------------------------------
extern "C" void kernel_launch(void* const* d_in, const int* in_sizes, int n_in,
                              void* d_out, int out_size)
{
    const float* hs = (const float*)d_in[0];
    const float* Wq = (const float*)d_in[1];
    const float* bq = (const float*)d_in[2];
    const float* Wk = (const float*)d_in[3];
    const float* bk = (const float*)d_in[4];
    const float* Wv = (const float*)d_in[5];
    const float* bv = (const float*)d_in[6];
    const float* Wo = (const float*)d_in[7];
    const float* bo = (const float*)d_in[8];
    float* out = (float*)d_out;

    float *q, *k, *v, *attn, *hsr, *wqr, *wkr, *wvr, *wor;
    cudaGetSymbolAddress((void**)&q,    g_q);
    cudaGetSymbolAddress((void**)&k,    g_k);
    cudaGetSymbolAddress((void**)&v,    g_v);
    cudaGetSymbolAddress((void**)&attn, g_attn);
    cudaGetSymbolAddress((void**)&hsr,  g_hsr);
    cudaGetSymbolAddress((void**)&wqr,  g_wqr);
    cudaGetSymbolAddress((void**)&wkr,  g_wkr);
    cudaGetSymbolAddress((void**)&wvr,  g_wvr);
    cudaGetSymbolAddress((void**)&wor,  g_wor);

    // round all GEMM operands to tf32-nearest
    const int nHS4 = ML_ * D_ / 4;
    const int nW4  = D_ * D_ / 4;
    round_tf32_kernel<<<2048, 256>>>(hs, hsr, nHS4);
    round_tf32_kernel<<<2048, 256>>>(Wq, wqr, nW4);
    round_tf32_kernel<<<2048, 256>>>(Wk, wkr, nW4);
    round_tf32_kernel<<<2048, 256>>>(Wv, wvr, nW4);
    round_tf32_kernel<<<2048, 256>>>(Wo, wor, nW4);

    cudaFuncSetAttribute(gemm_tf32mma,
                         cudaFuncAttributeMaxDynamicSharedMemorySize, GEMM_SMEM);
    dim3 gg(D_ / 128, ML_ / 128);   // (16, 32)
    gemm_tf32mma<<<gg, 256, GEMM_SMEM>>>(hsr, wqr, bq, q);
    gemm_tf32mma<<<gg, 256, GEMM_SMEM>>>(hsr, wkr, bk, k);
    gemm_tf32mma<<<gg, 256, GEMM_SMEM>>>(hsr, wvr, bv, v);

    size_t smem = (size_t)3 * 128 * AST * sizeof(float);  // 202,752 B
    cudaFuncSetAttribute(attn_mma,
                         cudaFuncAttributeMaxDynamicSharedMemorySize,
                         (int)smem);
    attn_mma<<<dim3(L_ / 128, BH_), 256, smem>>>(q, k, v, attn);

    gemm_tf32mma<<<gg, 256, GEMM_SMEM>>>(attn, wor, bo, out);
}

// round 9
// speedup vs baseline: 5.5803x; 1.0644x over previous
#include <cuda_runtime.h>
#include <cstdint>

// Problem constants
#define B_   2
#define L_   2048
#define D_   2048
#define NH_  16
#define HD_  128
#define BH_  (B_ * NH_)
#define ML_  (B_ * L_)          // 4096 rows for projections

// ---------------------------------------------------------------------------
// Scratch (static device allocations; no cudaMalloc allowed)
// ---------------------------------------------------------------------------
__device__ __align__(1024) float g_q[(size_t)ML_ * D_];
__device__ __align__(1024) float g_k[(size_t)ML_ * D_];
__device__ __align__(1024) float g_v[(size_t)ML_ * D_];
__device__ __align__(1024) float g_attn[(size_t)ML_ * D_];
__device__ __align__(1024) float g_hsr[(size_t)ML_ * D_];
__device__ __align__(1024) float g_wqr[(size_t)D_ * D_];
__device__ __align__(1024) float g_wkr[(size_t)D_ * D_];
__device__ __align__(1024) float g_wvr[(size_t)D_ * D_];
__device__ __align__(1024) float g_wor[(size_t)D_ * D_];

// attention scale folded with log2(e) so softmax uses exp2
#define ATT_QSCALE (0.08838834764831845f * 1.4426950408889634f)

// ---------------------------------------------------------------------------
// Helpers
// ---------------------------------------------------------------------------
__device__ __forceinline__ uint32_t smem_u32(const void* p) {
    uint32_t a;
    asm("{ .reg .u64 t; cvta.to.shared.u64 t, %1; cvt.u32.u64 %0, t; }"
        : "=r"(a) : "l"(p));
    return a;
}

__device__ __forceinline__ float tf32r(float x) {
    uint32_t u;
    asm("cvt.rna.tf32.f32 %0, %1;" : "=r"(u) : "f"(x));
    return __uint_as_float(u);
}

#define CP_ASYNC16(dst, src) \
    asm volatile("cp.async.cg.shared.global [%0], [%1], 16;" \
                 :: "r"(dst), "l"(src) : "memory")
#define CP_COMMIT() asm volatile("cp.async.commit_group;" ::: "memory")
#define CP_WAIT1()  asm volatile("cp.async.wait_group 1;" ::: "memory")

// mma.sync m16n8k8 tf32: D += A*B, A row-major m16k8, B col-major k8n8
#define MMA_TF32_16N8K8(c, a, b) \
    asm volatile("mma.sync.aligned.m16n8k8.row.col.f32.tf32.tf32.f32 " \
                 "{%0,%1,%2,%3}, {%4,%5,%6,%7}, {%8,%9}, {%0,%1,%2,%3};" \
                 : "+f"((c)[0]), "+f"((c)[1]), "+f"((c)[2]), "+f"((c)[3]) \
                 : "r"((a)[0]), "r"((a)[1]), "r"((a)[2]), "r"((a)[3]), \
                   "r"((b)[0]), "r"((b)[1]))

// ---------------------------------------------------------------------------
// Round-to-tf32 copy kernel (rounds GEMM operands to tf32-nearest once)
// ---------------------------------------------------------------------------
__global__ void round_tf32_kernel(const float* __restrict__ in,
                                  float* __restrict__ out, int n4)
{
    int i = blockIdx.x * blockDim.x + threadIdx.x;
    int stride = gridDim.x * blockDim.x;
    for (; i < n4; i += stride) {
        float4 v = ((const float4*)in)[i];
        v.x = tf32r(v.x); v.y = tf32r(v.y);
        v.z = tf32r(v.z); v.w = tf32r(v.w);
        ((float4*)out)[i] = v;
    }
}

// ---------------------------------------------------------------------------
// HMMA tf32 GEMM: C[M,2048] = A[M,2048] @ W[2048,2048]^T + bias
// BM=BN=128, BK=32, 3-stage cp.async pipeline, 256 threads = 8 warps.
// gridDim.z selects one of up to 3 (W, bias, C) problem instances -> the
// Q/K/V projections run as ONE launch (better wave packing).
// Smem rows padded to 36 floats; frag LDS conflict-free (4g+tg pattern).
// ---------------------------------------------------------------------------
#define GBK     32
#define GSTG    3
#define ROWPAD  36
#define TILE_FLOATS (128 * ROWPAD)            // 4608 floats
#define STAGE_FLOATS (2 * TILE_FLOATS)        // 9216 floats
#define GEMM_SMEM (GSTG * STAGE_FLOATS * 4)   // 110592 bytes

__global__ __launch_bounds__(256, 2)
void gemm_tf32mma(const float* __restrict__ A,
                  const float* __restrict__ W0, const float* __restrict__ W1,
                  const float* __restrict__ W2,
                  const float* __restrict__ b0, const float* __restrict__ b1,
                  const float* __restrict__ b2,
                  float* __restrict__ C0, float* __restrict__ C1,
                  float* __restrict__ C2)
{
    extern __shared__ __align__(1024) float smf[];
    const uint32_t sb = smem_u32(smf);

    const int z = blockIdx.z;
    const float* W    = (z == 0) ? W0 : (z == 1) ? W1 : W2;
    const float* bias = (z == 0) ? b0 : (z == 1) ? b1 : b2;
    float*       C    = (z == 0) ? C0 : (z == 1) ? C1 : C2;

    const int tid  = threadIdx.x;
    const int wid  = tid >> 5;
    const int lane = tid & 31;
    const int g    = lane >> 2;
    const int tg   = lane & 3;
    const int wr   = wid >> 1;
    const int wc   = wid & 1;

    const int row0 = blockIdx.y * 128;
    const int col0 = blockIdx.x * 128;
    const int K    = D_;
    const int NIT  = K / GBK;                  // 64

    const float* Ab = A + (size_t)row0 * K;
    const float* Wb = W + (size_t)col0 * K;

    // per-thread cp.async assignment: 8 chunks of 16B
    // idx in [0,2048): first 1024 = A tile, next 1024 = B tile
    // chunk -> (row = id2>>3, c16 = id2&7)
    int c_isB[8], c_row[8], c_c4[8];
    #pragma unroll
    for (int p = 0; p < 8; p++) {
        int idx = p * 256 + tid;
        c_isB[p] = idx >= 1024;
        int id2  = idx & 1023;
        c_row[p] = id2 >> 3;
        c_c4[p]  = id2 & 7;
    }

    auto issue = [&](int s, int it) {
        const int k0 = it * GBK;
        #pragma unroll
        for (int p = 0; p < 8; p++) {
            const float* src = (c_isB[p] ? Wb : Ab)
                               + (size_t)c_row[p] * K + k0 + c_c4[p] * 4;
            uint32_t dst = sb + (uint32_t)(s * STAGE_FLOATS
                              + c_isB[p] * TILE_FLOATS
                              + c_row[p] * ROWPAD + c_c4[p] * 4) * 4u;
            CP_ASYNC16(dst, src);
        }
    };

    float acc[2][8][4];
    #pragma unroll
    for (int mt = 0; mt < 2; mt++)
        #pragma unroll
        for (int nt = 0; nt < 8; nt++)
            #pragma unroll
            for (int e = 0; e < 4; e++) acc[mt][nt][e] = 0.0f;

    // prefetch 2 stages
    issue(0, 0); CP_COMMIT();
    issue(1, 1); CP_COMMIT();

    int s = 0;
    for (int it = 0; it < NIT; it++) {
        CP_WAIT1();
        __syncthreads();

        const float* As = smf + s * STAGE_FLOATS;
        const float* Bs = As + TILE_FLOATS;

        #pragma unroll
        for (int ks = 0; ks < 4; ks++) {
            const int kb = ks * 8;
            uint32_t af[2][4];
            #pragma unroll
            for (int mt = 0; mt < 2; mt++) {
                const int rb = wr * 32 + mt * 16;
                af[mt][0] = __float_as_uint(As[(rb + g)     * ROWPAD + kb + tg]);
                af[mt][1] = __float_as_uint(As[(rb + g + 8) * ROWPAD + kb + tg]);
                af[mt][2] = __float_as_uint(As[(rb + g)     * ROWPAD + kb + tg + 4]);
                af[mt][3] = __float_as_uint(As[(rb + g + 8) * ROWPAD + kb + tg + 4]);
            }
            uint32_t bf[8][2];
            #pragma unroll
            for (int nt = 0; nt < 8; nt++) {
                const int cb = wc * 64 + nt * 8;
                bf[nt][0] = __float_as_uint(Bs[(cb + g) * ROWPAD + kb + tg]);
                bf[nt][1] = __float_as_uint(Bs[(cb + g) * ROWPAD + kb + tg + 4]);
            }
            #pragma unroll
            for (int mt = 0; mt < 2; mt++)
                #pragma unroll
                for (int nt = 0; nt < 8; nt++)
                    MMA_TF32_16N8K8(acc[mt][nt], af[mt], bf[nt]);
        }

        __syncthreads();
        if (it + 2 < NIT) {
            int sn = s + 2; if (sn >= GSTG) sn -= GSTG;
            issue(sn, it + 2);
        }
        CP_COMMIT();
        s = (s + 1 == GSTG) ? 0 : s + 1;
    }

    // epilogue: bias add + store
    #pragma unroll
    for (int mt = 0; mt < 2; mt++) {
        const int r0 = row0 + wr * 32 + mt * 16 + g;
        #pragma unroll
        for (int nt = 0; nt < 8; nt++) {
            const int c = col0 + wc * 64 + nt * 8 + tg * 2;
            float2 bb = *(const float2*)&bias[c];
            float2 o0 = make_float2(acc[mt][nt][0] + bb.x, acc[mt][nt][1] + bb.y);
            float2 o1 = make_float2(acc[mt][nt][2] + bb.x, acc[mt][nt][3] + bb.y);
            *(float2*)&C[(size_t)r0 * D_ + c]       = o0;
            *(float2*)&C[(size_t)(r0 + 8) * D_ + c] = o1;
        }
    }
}

// ---------------------------------------------------------------------------
// Fast exp2 on the FMA pipe. |err| ~2e-6 rel.
// ---------------------------------------------------------------------------
__device__ __forceinline__ float exp2p(float y) {
    y = fmaxf(y, -120.0f);
    float t = y + 12582912.0f;
    int   i = __float_as_int(t);
    float f = y - (t - 12582912.0f);
    float p = 1.3333558e-3f;
    p = fmaf(p, f, 9.6181291e-3f);
    p = fmaf(p, f, 5.5504109e-2f);
    p = fmaf(p, f, 2.4022651e-1f);
    p = fmaf(p, f, 6.9314718e-1f);
    p = fmaf(p, f, 1.0f);
    return __int_as_float(__float_as_int(p) + (i << 23));
}

// ---------------------------------------------------------------------------
// Flash attention with tf32 mma.sync (causal). BM=BN=128, HD=128.
// qb reversed (heavy tiles scheduled first) to shorten the last wave.
// ---------------------------------------------------------------------------
#define AST 132

extern __shared__ float satt[];

__global__ __launch_bounds__(256, 1)
void attn_mma(const float* __restrict__ Q, const float* __restrict__ K,
              const float* __restrict__ V, float* __restrict__ O)
{
    float* Qs  = satt;                       // 128 x AST
    float* KVs = satt + 128 * AST;           // K natural, then V transposed
    float* Ps  = satt + 2 * 128 * AST;       // P [r][j]

    const int tid  = threadIdx.x;
    const int w    = tid >> 5;
    const int lane = tid & 31;
    const int g    = lane >> 2;
    const int tg   = lane & 3;
    const int rb   = w * 16;                 // warp's query-row base in tile

    const int qb = gridDim.x - 1 - blockIdx.x;   // heavy-first schedule
    const int bh = blockIdx.y;
    const int b  = bh / NH_;
    const int h  = bh % NH_;
    const int q0 = qb * 128;
    const size_t base = (size_t)b * L_ * D_ + (size_t)h * HD_;

    // ---- load Q tile: natural [r][d], scaled + tf32-rounded ----
    #pragma unroll
    for (int it = 0; it < 16; it++) {
        int idx = it * 256 + tid;
        int r   = idx >> 5;
        int c4  = (idx & 31) << 2;
        float4 qv = *(const float4*)(Q + base + (size_t)(q0 + r) * D_ + c4);
        float4 o;
        o.x = tf32r(qv.x * ATT_QSCALE); o.y = tf32r(qv.y * ATT_QSCALE);
        o.z = tf32r(qv.z * ATT_QSCALE); o.w = tf32r(qv.w * ATT_QSCALE);
        *(float4*)&Qs[r * AST + c4] = o;
    }

    float o_[16][4];
    float m0 = -3.0e38f, m1 = -3.0e38f, l0 = 0.0f, l1 = 0.0f;
    #pragma unroll
    for (int nt = 0; nt < 16; nt++)
        #pragma unroll
        for (int e = 0; e < 4; e++) o_[nt][e] = 0.0f;

    for (int t = 0; t <= qb; t++) {
        const int n0 = t * 128;

        // ---- load K tile natural [c][d], tf32-rounded ----
        __syncthreads();   // prior PV done reading KVs
        #pragma unroll
        for (int it = 0; it < 16; it++) {
            int idx = it * 256 + tid;
            int c   = idx >> 5;
            int c4  = (idx & 31) << 2;
            float4 kv = *(const float4*)(K + base + (size_t)(n0 + c) * D_ + c4);
            float4 o;
            o.x = tf32r(kv.x); o.y = tf32r(kv.y);
            o.z = tf32r(kv.z); o.w = tf32r(kv.w);
            *(float4*)&KVs[c * AST + c4] = o;
        }
        __syncthreads();

        // ---- S = Q K^T via mma (scores in log2 units) ----
        float sf[16][4];
        #pragma unroll
        for (int nt = 0; nt < 16; nt++)
            #pragma unroll
            for (int e = 0; e < 4; e++) sf[nt][e] = 0.0f;

        #pragma unroll
        for (int ks = 0; ks < 16; ks++) {
            const int kb = ks * 8;
            uint32_t af[4];
            af[0] = __float_as_uint(Qs[(rb + g)     * AST + kb + tg]);
            af[1] = __float_as_uint(Qs[(rb + g + 8) * AST + kb + tg]);
            af[2] = __float_as_uint(Qs[(rb + g)     * AST + kb + tg + 4]);
            af[3] = __float_as_uint(Qs[(rb + g + 8) * AST + kb + tg + 4]);
            #pragma unroll
            for (int nt = 0; nt < 16; nt++) {
                uint32_t bf[2];
                bf[0] = __float_as_uint(KVs[(nt * 8 + g) * AST + kb + tg]);
                bf[1] = __float_as_uint(KVs[(nt * 8 + g) * AST + kb + tg + 4]);
                MMA_TF32_16N8K8(sf[nt], af, bf);
            }
        }

        // ---- causal mask on diagonal tile ----
        if (t == qb) {
            #pragma unroll
            for (int nt = 0; nt < 16; nt++) {
                const int c0 = nt * 8 + 2 * tg;
                const int r0r = rb + g, r1r = rb + g + 8;
                if (r0r < c0)     sf[nt][0] = -1.0e30f;
                if (r0r < c0 + 1) sf[nt][1] = -1.0e30f;
                if (r1r < c0)     sf[nt][2] = -1.0e30f;
                if (r1r < c0 + 1) sf[nt][3] = -1.0e30f;
            }
        }

        // ---- online softmax on fragments ----
        float ml0 = -3.0e38f, ml1 = -3.0e38f;
        #pragma unroll
        for (int nt = 0; nt < 16; nt++) {
            ml0 = fmaxf(ml0, fmaxf(sf[nt][0], sf[nt][1]));
            ml1 = fmaxf(ml1, fmaxf(sf[nt][2], sf[nt][3]));
        }
        ml0 = fmaxf(ml0, __shfl_xor_sync(0xffffffffu, ml0, 1));
        ml0 = fmaxf(ml0, __shfl_xor_sync(0xffffffffu, ml0, 2));
        ml1 = fmaxf(ml1, __shfl_xor_sync(0xffffffffu, ml1, 1));
        ml1 = fmaxf(ml1, __shfl_xor_sync(0xffffffffu, ml1, 2));

        const float mn0 = fmaxf(m0, ml0), mn1 = fmaxf(m1, ml1);
        const float a0 = exp2p(m0 - mn0), a1 = exp2p(m1 - mn1);
        float rs0 = 0.0f, rs1 = 0.0f;
        #pragma unroll
        for (int nt = 0; nt < 16; nt++) {
            float p0 = exp2p(sf[nt][0] - mn0);
            float p1 = exp2p(sf[nt][1] - mn0);
            float p2 = exp2p(sf[nt][2] - mn1);
            float p3 = exp2p(sf[nt][3] - mn1);
            rs0 += p0 + p1; rs1 += p2 + p3;
            *(float2*)&Ps[(rb + g)     * AST + nt * 8 + 2 * tg] =
                make_float2(tf32r(p0), tf32r(p1));
            *(float2*)&Ps[(rb + g + 8) * AST + nt * 8 + 2 * tg] =
                make_float2(tf32r(p2), tf32r(p3));
        }
        rs0 += __shfl_xor_sync(0xffffffffu, rs0, 1);
        rs0 += __shfl_xor_sync(0xffffffffu, rs0, 2);
        rs1 += __shfl_xor_sync(0xffffffffu, rs1, 1);
        rs1 += __shfl_xor_sync(0xffffffffu, rs1, 2);
        l0 = l0 * a0 + rs0; l1 = l1 * a1 + rs1;
        m0 = mn0; m1 = mn1;
        #pragma unroll
        for (int nt = 0; nt < 16; nt++) {
            o_[nt][0] *= a0; o_[nt][1] *= a0;
            o_[nt][2] *= a1; o_[nt][3] *= a1;
        }

        // ---- load V tile transposed [c][j], tf32-rounded ----
        __syncthreads();   // QK done reading K; Ps writes now visible to all
        #pragma unroll
        for (int it = 0; it < 16; it++) {
            int idx = it * 256 + tid;
            int j   = (idx >> 3) & 127;
            int c4  = ((idx & 7) << 2) + ((idx >> 10) << 5);
            float4 vv = *(const float4*)(V + base + (size_t)(n0 + j) * D_ + c4);
            KVs[(c4 + 0) * AST + j] = tf32r(vv.x);
            KVs[(c4 + 1) * AST + j] = tf32r(vv.y);
            KVs[(c4 + 2) * AST + j] = tf32r(vv.z);
            KVs[(c4 + 3) * AST + j] = tf32r(vv.w);
        }
        __syncthreads();

        // ---- O += P @ V via mma ----
        #pragma unroll
        for (int ks = 0; ks < 16; ks++) {
            const int kb = ks * 8;
            uint32_t af[4];
            af[0] = __float_as_uint(Ps[(rb + g)     * AST + kb + tg]);
            af[1] = __float_as_uint(Ps[(rb + g + 8) * AST + kb + tg]);
            af[2] = __float_as_uint(Ps[(rb + g)     * AST + kb + tg + 4]);
            af[3] = __float_as_uint(Ps[(rb + g + 8) * AST + kb + tg + 4]);
            #pragma unroll
            for (int nt = 0; nt < 16; nt++) {
                uint32_t bf[2];
                bf[0] = __float_as_uint(KVs[(nt * 8 + g) * AST + kb + tg]);
                bf[1] = __float_as_uint(KVs[(nt * 8 + g) * AST + kb + tg + 4]);
                MMA_TF32_16N8K8(o_[nt], af, bf);
            }
        }
    }

    // ---- epilogue: normalize + tf32-round + write ----
    const float inv0 = 1.0f / l0, inv1 = 1.0f / l1;
    const int gr0 = q0 + rb + g, gr1 = gr0 + 8;
    #pragma unroll
    for (int nt = 0; nt < 16; nt++) {
        const int c = nt * 8 + 2 * tg;
        *(float2*)&O[base + (size_t)gr0 * D_ + c] =
            make_float2(tf32r(o_[nt][0] * inv0), tf32r(o_[nt][1] * inv0));
        *(float2*)&O[base + (size_t)gr1 * D_ + c] =
            make_float2(tf32r(o_[nt][2] * inv1), tf32r(o_[nt][3] * inv1));
    }
}

// ---------------------------------------------------------------------------
// Launcher
// ---------------------------------------------------------------------------
extern "C" void kernel_launch(void* const* d_in, const int* in_sizes, int n_in,
                              void* d_out, int out_size)
{
    const float* hs = (const float*)d_in[0];
    const float* Wq = (const float*)d_in[1];
    const float* bq = (const float*)d_in[2];
    const float* Wk = (const float*)d_in[3];
    const float* bk = (const float*)d_in[4];
    const float* Wv = (const float*)d_in[5];
    const float* bv = (const float*)d_in[6];
    const float* Wo = (const float*)d_in[7];
    const float* bo = (const float*)d_in[8];
    float* out = (float*)d_out;

    float *q, *k, *v, *attn, *hsr, *wqr, *wkr, *wvr, *wor;
    cudaGetSymbolAddress((void**)&q,    g_q);
    cudaGetSymbolAddress((void**)&k,    g_k);
    cudaGetSymbolAddress((void**)&v,    g_v);
    cudaGetSymbolAddress((void**)&attn, g_attn);
    cudaGetSymbolAddress((void**)&hsr,  g_hsr);
    cudaGetSymbolAddress((void**)&wqr,  g_wqr);
    cudaGetSymbolAddress((void**)&wkr,  g_wkr);
    cudaGetSymbolAddress((void**)&wvr,  g_wvr);
    cudaGetSymbolAddress((void**)&wor,  g_wor);

    // round all GEMM operands to tf32-nearest
    const int nHS4 = ML_ * D_ / 4;
    const int nW4  = D_ * D_ / 4;
    round_tf32_kernel<<<2048, 256>>>(hs, hsr, nHS4);
    round_tf32_kernel<<<2048, 256>>>(Wq, wqr, nW4);
    round_tf32_kernel<<<2048, 256>>>(Wk, wkr, nW4);
    round_tf32_kernel<<<2048, 256>>>(Wv, wvr, nW4);
    round_tf32_kernel<<<2048, 256>>>(Wo, wor, nW4);

    cudaFuncSetAttribute(gemm_tf32mma,
                         cudaFuncAttributeMaxDynamicSharedMemorySize, GEMM_SMEM);

    // fused Q/K/V projection: one launch, gridDim.z picks the instance
    dim3 gqkv(D_ / 128, ML_ / 128, 3);   // (16, 32, 3)
    gemm_tf32mma<<<gqkv, 256, GEMM_SMEM>>>(hsr, wqr, wkr, wvr,
                                           bq, bk, bv, q, k, v);

    size_t smem = (size_t)3 * 128 * AST * sizeof(float);  // 202,752 B
    cudaFuncSetAttribute(attn_mma,
                         cudaFuncAttributeMaxDynamicSharedMemorySize,
                         (int)smem);
    attn_mma<<<dim3(L_ / 128, BH_), 256, smem>>>(q, k, v, attn);

    // O-projection
    dim3 go(D_ / 128, ML_ / 128, 1);
    gemm_tf32mma<<<go, 256, GEMM_SMEM>>>(attn, wor, wor, wor,
                                         bo, bo, bo, out, out, out);
}

// round 10
// speedup vs baseline: 5.6025x; 1.0040x over previous
#include <cuda_runtime.h>
#include <cstdint>

// Problem constants
#define B_   2
#define L_   2048
#define D_   2048
#define NH_  16
#define HD_  128
#define BH_  (B_ * NH_)
#define ML_  (B_ * L_)          // 4096 rows for projections

// ---------------------------------------------------------------------------
// Scratch (static device allocations; no cudaMalloc allowed)
// ---------------------------------------------------------------------------
__device__ __align__(1024) float g_q[(size_t)ML_ * D_];
__device__ __align__(1024) float g_k[(size_t)ML_ * D_];
__device__ __align__(1024) float g_v[(size_t)ML_ * D_];
__device__ __align__(1024) float g_attn[(size_t)ML_ * D_];
__device__ __align__(1024) float g_hsr[(size_t)ML_ * D_];
__device__ __align__(1024) float g_wqr[(size_t)D_ * D_];
__device__ __align__(1024) float g_wkr[(size_t)D_ * D_];
__device__ __align__(1024) float g_wvr[(size_t)D_ * D_];
__device__ __align__(1024) float g_wor[(size_t)D_ * D_];

// attention scale folded with log2(e) so softmax uses exp2
#define ATT_QSCALE (0.08838834764831845f * 1.4426950408889634f)

// ---------------------------------------------------------------------------
// Helpers
// ---------------------------------------------------------------------------
__device__ __forceinline__ uint32_t smem_u32(const void* p) {
    uint32_t a;
    asm("{ .reg .u64 t; cvta.to.shared.u64 t, %1; cvt.u32.u64 %0, t; }"
        : "=r"(a) : "l"(p));
    return a;
}

__device__ __forceinline__ float tf32r(float x) {
    uint32_t u;
    asm("cvt.rna.tf32.f32 %0, %1;" : "=r"(u) : "f"(x));
    return __uint_as_float(u);
}

#define CP_ASYNC16(dst, src) \
    asm volatile("cp.async.cg.shared.global [%0], [%1], 16;" \
                 :: "r"(dst), "l"(src) : "memory")
#define CP_COMMIT() asm volatile("cp.async.commit_group;" ::: "memory")
#define CP_WAIT1()  asm volatile("cp.async.wait_group 1;" ::: "memory")
#define CP_WAIT0()  asm volatile("cp.async.wait_group 0;" ::: "memory")

// mma.sync m16n8k8 tf32: D += A*B, A row-major m16k8, B col-major k8n8
#define MMA_TF32_16N8K8(c, a, b) \
    asm volatile("mma.sync.aligned.m16n8k8.row.col.f32.tf32.tf32.f32 " \
                 "{%0,%1,%2,%3}, {%4,%5,%6,%7}, {%8,%9}, {%0,%1,%2,%3};" \
                 : "+f"((c)[0]), "+f"((c)[1]), "+f"((c)[2]), "+f"((c)[3]) \
                 : "r"((a)[0]), "r"((a)[1]), "r"((a)[2]), "r"((a)[3]), \
                   "r"((b)[0]), "r"((b)[1]))

// ---------------------------------------------------------------------------
// Round-to-tf32 copy kernel (rounds GEMM operands to tf32-nearest once)
// ---------------------------------------------------------------------------
__global__ void round_tf32_kernel(const float* __restrict__ in,
                                  float* __restrict__ out, int n4)
{
    int i = blockIdx.x * blockDim.x + threadIdx.x;
    int stride = gridDim.x * blockDim.x;
    for (; i < n4; i += stride) {
        float4 v = ((const float4*)in)[i];
        v.x = tf32r(v.x); v.y = tf32r(v.y);
        v.z = tf32r(v.z); v.w = tf32r(v.w);
        ((float4*)out)[i] = v;
    }
}

// ---------------------------------------------------------------------------
// HMMA tf32 GEMM: C[M,2048] = A[M,2048] @ W[2048,2048]^T + bias
// BM=BN=128, BK=32, 3-stage cp.async pipeline, 256 threads = 8 warps.
// gridDim.z selects one of up to 3 (W, bias, C) instances (fused QKV launch).
// z==0 output is additionally scaled by scale0; do_round rounds outputs to
// tf32 (used when the output feeds another tf32 MMA).
// ---------------------------------------------------------------------------
#define GBK     32
#define GSTG    3
#define ROWPAD  36
#define TILE_FLOATS (128 * ROWPAD)            // 4608 floats
#define STAGE_FLOATS (2 * TILE_FLOATS)        // 9216 floats
#define GEMM_SMEM (GSTG * STAGE_FLOATS * 4)   // 110592 bytes

__global__ __launch_bounds__(256, 2)
void gemm_tf32mma(const float* __restrict__ A,
                  const float* __restrict__ W0, const float* __restrict__ W1,
                  const float* __restrict__ W2,
                  const float* __restrict__ b0, const float* __restrict__ b1,
                  const float* __restrict__ b2,
                  float* __restrict__ C0, float* __restrict__ C1,
                  float* __restrict__ C2,
                  float scale0, int do_round)
{
    extern __shared__ __align__(1024) float smf[];
    const uint32_t sb = smem_u32(smf);

    const int z = blockIdx.z;
    const float* W    = (z == 0) ? W0 : (z == 1) ? W1 : W2;
    const float* bias = (z == 0) ? b0 : (z == 1) ? b1 : b2;
    float*       C    = (z == 0) ? C0 : (z == 1) ? C1 : C2;
    const float  esc  = (z == 0) ? scale0 : 1.0f;

    const int tid  = threadIdx.x;
    const int wid  = tid >> 5;
    const int lane = tid & 31;
    const int g    = lane >> 2;
    const int tg   = lane & 3;
    const int wr   = wid >> 1;
    const int wc   = wid & 1;

    const int row0 = blockIdx.y * 128;
    const int col0 = blockIdx.x * 128;
    const int K    = D_;
    const int NIT  = K / GBK;                  // 64

    const float* Ab = A + (size_t)row0 * K;
    const float* Wb = W + (size_t)col0 * K;

    int c_isB[8], c_row[8], c_c4[8];
    #pragma unroll
    for (int p = 0; p < 8; p++) {
        int idx = p * 256 + tid;
        c_isB[p] = idx >= 1024;
        int id2  = idx & 1023;
        c_row[p] = id2 >> 3;
        c_c4[p]  = id2 & 7;
    }

    auto issue = [&](int s, int it) {
        const int k0 = it * GBK;
        #pragma unroll
        for (int p = 0; p < 8; p++) {
            const float* src = (c_isB[p] ? Wb : Ab)
                               + (size_t)c_row[p] * K + k0 + c_c4[p] * 4;
            uint32_t dst = sb + (uint32_t)(s * STAGE_FLOATS
                              + c_isB[p] * TILE_FLOATS
                              + c_row[p] * ROWPAD + c_c4[p] * 4) * 4u;
            CP_ASYNC16(dst, src);
        }
    };

    float acc[2][8][4];
    #pragma unroll
    for (int mt = 0; mt < 2; mt++)
        #pragma unroll
        for (int nt = 0; nt < 8; nt++)
            #pragma unroll
            for (int e = 0; e < 4; e++) acc[mt][nt][e] = 0.0f;

    issue(0, 0); CP_COMMIT();
    issue(1, 1); CP_COMMIT();

    int s = 0;
    for (int it = 0; it < NIT; it++) {
        CP_WAIT1();
        __syncthreads();

        const float* As = smf + s * STAGE_FLOATS;
        const float* Bs = As + TILE_FLOATS;

        #pragma unroll
        for (int ks = 0; ks < 4; ks++) {
            const int kb = ks * 8;
            uint32_t af[2][4];
            #pragma unroll
            for (int mt = 0; mt < 2; mt++) {
                const int rb = wr * 32 + mt * 16;
                af[mt][0] = __float_as_uint(As[(rb + g)     * ROWPAD + kb + tg]);
                af[mt][1] = __float_as_uint(As[(rb + g + 8) * ROWPAD + kb + tg]);
                af[mt][2] = __float_as_uint(As[(rb + g)     * ROWPAD + kb + tg + 4]);
                af[mt][3] = __float_as_uint(As[(rb + g + 8) * ROWPAD + kb + tg + 4]);
            }
            uint32_t bf[8][2];
            #pragma unroll
            for (int nt = 0; nt < 8; nt++) {
                const int cb = wc * 64 + nt * 8;
                bf[nt][0] = __float_as_uint(Bs[(cb + g) * ROWPAD + kb + tg]);
                bf[nt][1] = __float_as_uint(Bs[(cb + g) * ROWPAD + kb + tg + 4]);
            }
            #pragma unroll
            for (int mt = 0; mt < 2; mt++)
                #pragma unroll
                for (int nt = 0; nt < 8; nt++)
                    MMA_TF32_16N8K8(acc[mt][nt], af[mt], bf[nt]);
        }

        __syncthreads();
        if (it + 2 < NIT) {
            int sn = s + 2; if (sn >= GSTG) sn -= GSTG;
            issue(sn, it + 2);
        }
        CP_COMMIT();
        s = (s + 1 == GSTG) ? 0 : s + 1;
    }

    // epilogue: bias add (+ optional scale + tf32 round) + store
    #pragma unroll
    for (int mt = 0; mt < 2; mt++) {
        const int r0 = row0 + wr * 32 + mt * 16 + g;
        #pragma unroll
        for (int nt = 0; nt < 8; nt++) {
            const int c = col0 + wc * 64 + nt * 8 + tg * 2;
            float2 bb = *(const float2*)&bias[c];
            float2 o0 = make_float2((acc[mt][nt][0] + bb.x) * esc,
                                    (acc[mt][nt][1] + bb.y) * esc);
            float2 o1 = make_float2((acc[mt][nt][2] + bb.x) * esc,
                                    (acc[mt][nt][3] + bb.y) * esc);
            if (do_round) {
                o0.x = tf32r(o0.x); o0.y = tf32r(o0.y);
                o1.x = tf32r(o1.x); o1.y = tf32r(o1.y);
            }
            *(float2*)&C[(size_t)r0 * D_ + c]       = o0;
            *(float2*)&C[(size_t)(r0 + 8) * D_ + c] = o1;
        }
    }
}

// ---------------------------------------------------------------------------
// Fast exp2 on the FMA pipe. |err| ~2e-6 rel.
// ---------------------------------------------------------------------------
__device__ __forceinline__ float exp2p(float y) {
    y = fmaxf(y, -120.0f);
    float t = y + 12582912.0f;
    int   i = __float_as_int(t);
    float f = y - (t - 12582912.0f);
    float p = 1.3333558e-3f;
    p = fmaf(p, f, 9.6181291e-3f);
    p = fmaf(p, f, 5.5504109e-2f);
    p = fmaf(p, f, 2.4022651e-1f);
    p = fmaf(p, f, 6.9314718e-1f);
    p = fmaf(p, f, 1.0f);
    return __int_as_float(__float_as_int(p) + (i << 23));
}

// ---------------------------------------------------------------------------
// Flash attention, tf32 mma.sync, causal. BM=BN=128, HD=128, 8 warps.
// Inputs g_q/g_k/g_v are PRE-ROUNDED (and Q pre-scaled) by the GEMM epilogue:
//  - no per-tile conversions in this kernel
//  - K and V copied with cp.async in NATURAL layout (V stride 136 makes the
//    PV B-fragment pattern conflict-free without a transpose)
//  - Q fragments held in registers (loaded once via the K buffer)
//  - separate K/V buffers: V(t) loads during QK(t); K(t+1) during PV(t)
// ---------------------------------------------------------------------------
#define PST 132     // Ps stride (floats)
#define KVT 136     // K/V stride (floats); 136 % 32 == 8 -> natural-V frags OK

extern __shared__ float satt[];

__global__ __launch_bounds__(256, 1)
void attn_mma(const float* __restrict__ Q, const float* __restrict__ K,
              const float* __restrict__ V, float* __restrict__ O)
{
    float* Ps = satt;                          // 128 x 132
    float* Kb = satt + 128 * PST;              // 128 x 136
    float* Vb = satt + 128 * PST + 128 * KVT;  // 128 x 136
    const uint32_t sbase = smem_u32(satt);
    const uint32_t KbA = sbase + 128u * PST * 4u;
    const uint32_t VbA = KbA + 128u * KVT * 4u;

    const int tid  = threadIdx.x;
    const int w    = tid >> 5;
    const int lane = tid & 31;
    const int g    = lane >> 2;
    const int tg   = lane & 3;
    const int rb   = w * 16;

    const int qb = gridDim.x - 1 - blockIdx.x;   // heavy-first schedule
    const int bh = blockIdx.y;
    const int b  = bh / NH_;
    const int h  = bh % NH_;
    const int q0 = qb * 128;
    const size_t base = (size_t)b * L_ * D_ + (size_t)h * HD_;

    // 128x128 float tile = 4096 16B-chunks, 16 per thread
    auto load_tile = [&](uint32_t dstA, const float* src) {
        #pragma unroll
        for (int p = 0; p < 16; p++) {
            int idx = p * 256 + tid;
            int r   = idx >> 5;
            int c   = idx & 31;
            CP_ASYNC16(dstA + (uint32_t)(r * KVT + c * 4) * 4u,
                       src + (size_t)r * D_ + c * 4);
        }
    };

    // ---- prologue: stage Q through Kb, pull A-fragments into registers ----
    load_tile(KbA, Q + base + (size_t)q0 * D_);
    CP_COMMIT();
    CP_WAIT0();
    __syncthreads();
    uint32_t qf[16][4];
    #pragma unroll
    for (int ks = 0; ks < 16; ks++) {
        const int kb = ks * 8;
        qf[ks][0] = __float_as_uint(Kb[(rb + g)     * KVT + kb + tg]);
        qf[ks][1] = __float_as_uint(Kb[(rb + g + 8) * KVT + kb + tg]);
        qf[ks][2] = __float_as_uint(Kb[(rb + g)     * KVT + kb + tg + 4]);
        qf[ks][3] = __float_as_uint(Kb[(rb + g + 8) * KVT + kb + tg + 4]);
    }
    __syncthreads();
    load_tile(KbA, K + base);                  // K(0)
    CP_COMMIT();

    float o_[16][4];
    float m0 = -3.0e38f, m1 = -3.0e38f, l0 = 0.0f, l1 = 0.0f;
    #pragma unroll
    for (int nt = 0; nt < 16; nt++)
        #pragma unroll
        for (int e = 0; e < 4; e++) o_[nt][e] = 0.0f;

    for (int t = 0; t <= qb; t++) {
        const int n0 = t * 128;

        __syncthreads();                       // Vb free (prev PV done)
        load_tile(VbA, V + base + (size_t)n0 * D_);
        CP_COMMIT();
        CP_WAIT1();                            // K(t) landed (V(t) in flight)
        __syncthreads();

        // ---- S = Q K^T (scores in log2 units; Q pre-scaled) ----
        float sf[16][4];
        #pragma unroll
        for (int nt = 0; nt < 16; nt++)
            #pragma unroll
            for (int e = 0; e < 4; e++) sf[nt][e] = 0.0f;

        #pragma unroll
        for (int ks = 0; ks < 16; ks++) {
            const int kb = ks * 8;
            #pragma unroll
            for (int nt = 0; nt < 16; nt++) {
                uint32_t bf[2];
                bf[0] = __float_as_uint(Kb[(nt * 8 + g) * KVT + kb + tg]);
                bf[1] = __float_as_uint(Kb[(nt * 8 + g) * KVT + kb + tg + 4]);
                MMA_TF32_16N8K8(sf[nt], qf[ks], bf);
            }
        }

        // ---- causal mask on diagonal tile ----
        if (t == qb) {
            #pragma unroll
            for (int nt = 0; nt < 16; nt++) {
                const int c0 = nt * 8 + 2 * tg;
                const int r0r = rb + g, r1r = rb + g + 8;
                if (r0r < c0)     sf[nt][0] = -1.0e30f;
                if (r0r < c0 + 1) sf[nt][1] = -1.0e30f;
                if (r1r < c0)     sf[nt][2] = -1.0e30f;
                if (r1r < c0 + 1) sf[nt][3] = -1.0e30f;
            }
        }

        // ---- online softmax on fragments ----
        float ml0 = -3.0e38f, ml1 = -3.0e38f;
        #pragma unroll
        for (int nt = 0; nt < 16; nt++) {
            ml0 = fmaxf(ml0, fmaxf(sf[nt][0], sf[nt][1]));
            ml1 = fmaxf(ml1, fmaxf(sf[nt][2], sf[nt][3]));
        }
        ml0 = fmaxf(ml0, __shfl_xor_sync(0xffffffffu, ml0, 1));
        ml0 = fmaxf(ml0, __shfl_xor_sync(0xffffffffu, ml0, 2));
        ml1 = fmaxf(ml1, __shfl_xor_sync(0xffffffffu, ml1, 1));
        ml1 = fmaxf(ml1, __shfl_xor_sync(0xffffffffu, ml1, 2));

        const float mn0 = fmaxf(m0, ml0), mn1 = fmaxf(m1, ml1);
        const float a0 = exp2p(m0 - mn0), a1 = exp2p(m1 - mn1);
        float rs0 = 0.0f, rs1 = 0.0f;
        #pragma unroll
        for (int nt = 0; nt < 16; nt++) {
            float p0 = exp2p(sf[nt][0] - mn0);
            float p1 = exp2p(sf[nt][1] - mn0);
            float p2 = exp2p(sf[nt][2] - mn1);
            float p3 = exp2p(sf[nt][3] - mn1);
            rs0 += p0 + p1; rs1 += p2 + p3;
            *(float2*)&Ps[(rb + g)     * PST + nt * 8 + 2 * tg] =
                make_float2(tf32r(p0), tf32r(p1));
            *(float2*)&Ps[(rb + g + 8) * PST + nt * 8 + 2 * tg] =
                make_float2(tf32r(p2), tf32r(p3));
        }
        rs0 += __shfl_xor_sync(0xffffffffu, rs0, 1);
        rs0 += __shfl_xor_sync(0xffffffffu, rs0, 2);
        rs1 += __shfl_xor_sync(0xffffffffu, rs1, 1);
        rs1 += __shfl_xor_sync(0xffffffffu, rs1, 2);
        l0 = l0 * a0 + rs0; l1 = l1 * a1 + rs1;
        m0 = mn0; m1 = mn1;
        #pragma unroll
        for (int nt = 0; nt < 16; nt++) {
            o_[nt][0] *= a0; o_[nt][1] *= a0;
            o_[nt][2] *= a1; o_[nt][3] *= a1;
        }

        __syncthreads();                       // Kb free (QK reads done)
        if (t < qb) {
            load_tile(KbA, K + base + (size_t)(n0 + 128) * D_);   // K(t+1)
            CP_COMMIT();
            CP_WAIT1();                        // V(t) landed (K(t+1) in flight)
        } else {
            CP_WAIT0();                        // V(t) landed
        }
        __syncthreads();

        // ---- O += P @ V  (V natural layout; B-frag = V[k][n], banks 8tg+g) --
        #pragma unroll
        for (int ks = 0; ks < 16; ks++) {
            const int kb = ks * 8;
            uint32_t af[4];
            af[0] = __float_as_uint(Ps[(rb + g)     * PST + kb + tg]);
            af[1] = __float_as_uint(Ps[(rb + g + 8) * PST + kb + tg]);
            af[2] = __float_as_uint(Ps[(rb + g)     * PST + kb + tg + 4]);
            af[3] = __float_as_uint(Ps[(rb + g + 8) * PST + kb + tg + 4]);
            #pragma unroll
            for (int nt = 0; nt < 16; nt++) {
                uint32_t bf[2];
                bf[0] = __float_as_uint(Vb[(kb + tg)     * KVT + nt * 8 + g]);
                bf[1] = __float_as_uint(Vb[(kb + tg + 4) * KVT + nt * 8 + g]);
                MMA_TF32_16N8K8(o_[nt], af, bf);
            }
        }
    }

    // ---- epilogue: normalize + tf32-round + write ----
    const float inv0 = 1.0f / l0, inv1 = 1.0f / l1;
    const int gr0 = q0 + rb + g, gr1 = gr0 + 8;
    #pragma unroll
    for (int nt = 0; nt < 16; nt++) {
        const int c = nt * 8 + 2 * tg;
        *(float2*)&O[base + (size_t)gr0 * D_ + c] =
            make_float2(tf32r(o_[nt][0] * inv0), tf32r(o_[nt][1] * inv0));
        *(float2*)&O[base + (size_t)gr1 * D_ + c] =
            make_float2(tf32r(o_[nt][2] * inv1), tf32r(o_[nt][3] * inv1));
    }
}

#define ATTN_SMEM ((128 * PST + 2 * 128 * KVT) * 4)   // 206,848 bytes

// ---------------------------------------------------------------------------
// Launcher
// ---------------------------------------------------------------------------
extern "C" void kernel_launch(void* const* d_in, const int* in_sizes, int n_in,
                              void* d_out, int out_size)
{
    const float* hs = (const float*)d_in[0];
    const float* Wq = (const float*)d_in[1];
    const float* bq = (const float*)d_in[2];
    const float* Wk = (const float*)d_in[3];
    const float* bk = (const float*)d_in[4];
    const float* Wv = (const float*)d_in[5];
    const float* bv = (const float*)d_in[6];
    const float* Wo = (const float*)d_in[7];
    const float* bo = (const float*)d_in[8];
    float* out = (float*)d_out;

    float *q, *k, *v, *attn, *hsr, *wqr, *wkr, *wvr, *wor;
    cudaGetSymbolAddress((void**)&q,    g_q);
    cudaGetSymbolAddress((void**)&k,    g_k);
    cudaGetSymbolAddress((void**)&v,    g_v);
    cudaGetSymbolAddress((void**)&attn, g_attn);
    cudaGetSymbolAddress((void**)&hsr,  g_hsr);
    cudaGetSymbolAddress((void**)&wqr,  g_wqr);
    cudaGetSymbolAddress((void**)&wkr,  g_wkr);
    cudaGetSymbolAddress((void**)&wvr,  g_wvr);
    cudaGetSymbolAddress((void**)&wor,  g_wor);

    // round all GEMM operands to tf32-nearest
    const int nHS4 = ML_ * D_ / 4;
    const int nW4  = D_ * D_ / 4;
    round_tf32_kernel<<<2048, 256>>>(hs, hsr, nHS4);
    round_tf32_kernel<<<2048, 256>>>(Wq, wqr, nW4);
    round_tf32_kernel<<<2048, 256>>>(Wk, wkr, nW4);
    round_tf32_kernel<<<2048, 256>>>(Wv, wvr, nW4);
    round_tf32_kernel<<<2048, 256>>>(Wo, wor, nW4);

    cudaFuncSetAttribute(gemm_tf32mma,
                         cudaFuncAttributeMaxDynamicSharedMemorySize, GEMM_SMEM);

    // fused Q/K/V projection: outputs pre-rounded; Q pre-scaled
    dim3 gqkv(D_ / 128, ML_ / 128, 3);   // (16, 32, 3)
    gemm_tf32mma<<<gqkv, 256, GEMM_SMEM>>>(hsr, wqr, wkr, wvr,
                                           bq, bk, bv, q, k, v,
                                           (float)ATT_QSCALE, 1);

    cudaFuncSetAttribute(attn_mma,
                         cudaFuncAttributeMaxDynamicSharedMemorySize,
                         ATTN_SMEM);
    attn_mma<<<dim3(L_ / 128, BH_), 256, ATTN_SMEM>>>(q, k, v, attn);

    // O-projection: plain fp32 output, no scale, no rounding
    dim3 go(D_ / 128, ML_ / 128, 1);
    gemm_tf32mma<<<go, 256, GEMM_SMEM>>>(attn, wor, wor, wor,
                                         bo, bo, bo, out, out, out,
                                         1.0f, 0);
}